// round 1
// baseline (speedup 1.0000x reference)
#include <cuda_runtime.h>
#include <cuda_bf16.h>
#include <float.h>
#include <math.h>

// Problem constants
#define NTOK   2048          // N = F*H*W = 2*32*32
#define INNER  512
#define QKVW   1536          // 3*INNER
#define HEADS  8
#define DHEAD  64

// Scratch (device globals; no allocation allowed)
__device__ float g_qkv[NTOK * QKVW];    // rows = xp positions 0..N-1
__device__ float g_attn[NTOK * INNER];  // out_concat rows 0..N-1

// ---------------------------------------------------------------------------
// Tiled fp32 SGEMM: C[M,N] = A[M,K] @ B[K,N] (+ bias[N] if bias != nullptr)
// All dims must divide tile sizes evenly (they do here).
// ---------------------------------------------------------------------------
template <int BM, int BN, int BK, int TM, int TN>
__global__ void __launch_bounds__((BM / TM) * (BN / TN))
sgemm_kernel(const float* __restrict__ A, const float* __restrict__ B,
             float* __restrict__ C, const float* __restrict__ bias,
             int M, int N, int K) {
    constexpr int THREADS = (BM / TM) * (BN / TN);
    static_assert(BM * BK == THREADS * 4, "A load shape");
    static_assert(BK * BN == THREADS * 4, "B load shape");

    __shared__ float As[BK][BM];
    __shared__ float Bs[BK][BN];

    const int tid  = threadIdx.x;
    const int tcol = tid % (BN / TN);
    const int trow = tid / (BN / TN);

    // A loaded as float4 along K, stored transposed into As
    const int aRow = tid / (BK / 4);
    const int aCol = (tid % (BK / 4)) * 4;
    // B loaded as float4 along N
    const int bRow = tid / (BN / 4);
    const int bCol = (tid % (BN / 4)) * 4;

    A += (size_t)blockIdx.y * BM * K;
    B += (size_t)blockIdx.x * BN;
    C += (size_t)blockIdx.y * BM * N + (size_t)blockIdx.x * BN;

    float acc[TM][TN];
#pragma unroll
    for (int m = 0; m < TM; m++)
#pragma unroll
        for (int n = 0; n < TN; n++) acc[m][n] = 0.0f;

    float ra[TM], rb[TN];

    for (int k0 = 0; k0 < K; k0 += BK) {
        float4 av = *reinterpret_cast<const float4*>(A + (size_t)aRow * K + aCol);
        As[aCol + 0][aRow] = av.x;
        As[aCol + 1][aRow] = av.y;
        As[aCol + 2][aRow] = av.z;
        As[aCol + 3][aRow] = av.w;
        *reinterpret_cast<float4*>(&Bs[bRow][bCol]) =
            *reinterpret_cast<const float4*>(B + (size_t)bRow * N + bCol);
        __syncthreads();

        A += BK;
        B += (size_t)BK * N;

#pragma unroll
        for (int kk = 0; kk < BK; kk++) {
#pragma unroll
            for (int m = 0; m < TM; m++) ra[m] = As[kk][trow * TM + m];
#pragma unroll
            for (int n = 0; n < TN; n++) rb[n] = Bs[kk][tcol * TN + n];
#pragma unroll
            for (int m = 0; m < TM; m++)
#pragma unroll
                for (int n = 0; n < TN; n++) acc[m][n] = fmaf(ra[m], rb[n], acc[m][n]);
        }
        __syncthreads();
    }

#pragma unroll
    for (int m = 0; m < TM; m++) {
#pragma unroll
        for (int n = 0; n < TN; n++) {
            float v = acc[m][n];
            if (bias) v += bias[(size_t)blockIdx.x * BN + tcol * TN + n];
            C[(size_t)(trow * TM + m) * N + tcol * TN + n] = v;
        }
    }
}

// ---------------------------------------------------------------------------
// Attention: one block (256 thr = 8 warps) per query; warp w -> head w.
// Window = BOS + 125 stencil neighbors (5x5x5 over 2x32x32, causal nidx<=qi).
// Block 2047 copies v_bos into out row 0.
// ---------------------------------------------------------------------------
__device__ __forceinline__ float warpSum(float v) {
#pragma unroll
    for (int o = 16; o > 0; o >>= 1) v += __shfl_xor_sync(0xffffffffu, v, o);
    return v;
}
__device__ __forceinline__ float warpMax(float v) {
#pragma unroll
    for (int o = 16; o > 0; o >>= 1) v = fmaxf(v, __shfl_xor_sync(0xffffffffu, v, o));
    return v;
}

__global__ void __launch_bounds__(256)
attn_kernel(const float* __restrict__ qkv, float* __restrict__ out) {
    const int bid = blockIdx.x;
    const int tid = threadIdx.x;

    if (bid == 2047) {
        // out row 0 = v_bos = qkv[0, 1024:1536]
        for (int c = tid; c < INNER; c += blockDim.x) out[c] = qkv[2 * INNER + c];
        return;
    }

    const int qi   = bid;          // query index 0..2046 (xp pos qi+1)
    const int h    = tid >> 5;     // head
    const int lane = tid & 31;

    const float scale = 0.125f;    // DHEAD^-0.5
    const float* qrow = qkv + (size_t)(qi + 1) * QKVW + h * DHEAD;
    const float q0 = qrow[lane] * scale;
    const float q1 = qrow[lane + 32] * scale;

    const int f  = qi >> 10;
    const int yy = (qi >> 5) & 31;
    const int xx = qi & 31;

    const float* kbase = qkv + INNER + h * DHEAD;      // K block
    const float* vbase = qkv + 2 * INNER + h * DHEAD;  // V block

    // slot j: 0 = BOS, 1+jj = neighbor jj (jj = (df+2)*25+(dh+2)*5+(dw+2))
    float s[4] = {-FLT_MAX, -FLT_MAX, -FLT_MAX, -FLT_MAX};

    // BOS (slot 0): key = xp pos 0 = qkv row 0
    {
        float part = q0 * kbase[lane] + q1 * kbase[lane + 32];
        float val = warpSum(part);
        if (lane == 0) s[0] = val;
    }

#pragma unroll 5
    for (int jj = 0; jj < 125; jj++) {
        const int j  = jj + 1;
        const int df = jj / 25 - 2;
        const int dh = (jj / 5) % 5 - 2;
        const int dw = jj % 5 - 2;
        const int nf = f + df, nh = yy + dh, nw = xx + dw;
        bool valid = ((unsigned)nf < 2u) & ((unsigned)nh < 32u) & ((unsigned)nw < 32u);
        const int nidx = (nf << 10) + (nh << 5) + nw;
        valid = valid && (nidx <= qi);
        if (valid) {  // warp-uniform
            const float* kr = kbase + (size_t)(nidx + 1) * QKVW;
            float part = q0 * kr[lane] + q1 * kr[lane + 32];
            float val = warpSum(part);
            if (lane == (j & 31)) s[j >> 5] = val;
        }
    }

    // softmax over the 126 slots (lane l owns slots l, l+32, l+64, l+96)
    float m = fmaxf(fmaxf(s[0], s[1]), fmaxf(s[2], s[3]));
    m = warpMax(m);
    float z = 0.0f;
#pragma unroll
    for (int t = 0; t < 4; t++) {
        s[t] = __expf(s[t] - m);   // masked slots: exp(-huge) = 0
        z += s[t];
    }
    z = warpSum(z);
    const float invz = 1.0f / z;
#pragma unroll
    for (int t = 0; t < 4; t++) s[t] *= invz;   // s now holds probabilities

    float a0 = 0.0f, a1 = 0.0f;

    // BOS value
    {
        float p = __shfl_sync(0xffffffffu, s[0], 0);
        a0 = p * vbase[lane];
        a1 = p * vbase[lane + 32];
    }

#pragma unroll 5
    for (int jj = 0; jj < 125; jj++) {
        const int j  = jj + 1;
        const int df = jj / 25 - 2;
        const int dh = (jj / 5) % 5 - 2;
        const int dw = jj % 5 - 2;
        const int nf = f + df, nh = yy + dh, nw = xx + dw;
        bool valid = ((unsigned)nf < 2u) & ((unsigned)nh < 32u) & ((unsigned)nw < 32u);
        const int nidx = (nf << 10) + (nh << 5) + nw;
        valid = valid && (nidx <= qi);
        if (valid) {  // warp-uniform
            float p = __shfl_sync(0xffffffffu, s[j >> 5], j & 31);
            const float* vr = vbase + (size_t)(nidx + 1) * QKVW;
            a0 = fmaf(p, vr[lane], a0);
            a1 = fmaf(p, vr[lane + 32], a1);
        }
    }

    float* orow = out + (size_t)(qi + 1) * INNER + h * DHEAD;
    orow[lane] = a0;
    orow[lane + 32] = a1;
}

// ---------------------------------------------------------------------------
extern "C" void kernel_launch(void* const* d_in, const int* in_sizes, int n_in,
                              void* d_out, int out_size) {
    const float* x     = (const float*)d_in[0];  // (1, 2048, 512)
    const float* w_qkv = (const float*)d_in[1];  // (512, 1536)
    const float* w_out = (const float*)d_in[2];  // (512, 512)
    const float* b_out = (const float*)d_in[3];  // (512,)
    float* out = (float*)d_out;                  // (1, 2048, 512)

    float* qkv = nullptr;
    float* attn = nullptr;
    cudaGetSymbolAddress((void**)&qkv, g_qkv);
    cudaGetSymbolAddress((void**)&attn, g_attn);

    // 1) qkv = x @ w_qkv        (2048 x 1536 x K=512)
    {
        dim3 grid(QKVW / 128, NTOK / 128);
        sgemm_kernel<128, 128, 8, 8, 8><<<grid, 256>>>(x, w_qkv, qkv, nullptr,
                                                       NTOK, QKVW, INNER);
    }

    // 2) windowed causal attention -> g_attn (row 0 = v_bos copy)
    attn_kernel<<<2048, 256>>>(qkv, attn);

    // 3) out = g_attn @ w_out + b_out   (2048 x 512 x K=512)
    {
        dim3 grid(INNER / 64, NTOK / 64);
        sgemm_kernel<64, 64, 16, 4, 4><<<grid, 256>>>(attn, w_out, out, b_out,
                                                      NTOK, INNER, INNER);
    }
}

// round 3
// speedup vs baseline: 1.4188x; 1.4188x over previous
#include <cuda_runtime.h>
#include <cuda_bf16.h>
#include <cstdint>
#include <float.h>
#include <math.h>

// Problem constants
#define NTOK   2048          // N = F*H*W = 2*32*32
#define INNER  512
#define QKVW   1536          // 3*INNER
#define HEADS  8
#define DHEAD  64

// Scratch (device globals; no allocation allowed)
__device__ float g_qkv[NTOK * QKVW];
__device__ float g_attn[NTOK * INNER];
__device__ __nv_bfloat16 g_xhi[NTOK * INNER],  g_xlo[NTOK * INNER];
__device__ __nv_bfloat16 g_w1hi[INNER * QKVW], g_w1lo[INNER * QKVW];
__device__ __nv_bfloat16 g_ahi[NTOK * INNER],  g_alo[NTOK * INNER];
__device__ __nv_bfloat16 g_w2hi[INNER * INNER], g_w2lo[INNER * INNER];

// ---------------------------------------------------------------------------
// Split fp32 -> (hi, lo) bf16 pair:  hi = bf16(v), lo = bf16(v - hi)
// ---------------------------------------------------------------------------
__global__ void __launch_bounds__(256)
split_bf16_kernel(const float* __restrict__ in,
                  __nv_bfloat16* __restrict__ hi,
                  __nv_bfloat16* __restrict__ lo, int n) {
    int base = (blockIdx.x * 256 + threadIdx.x) * 4;
    if (base < n) {
        float4 v = *reinterpret_cast<const float4*>(in + base);
        float vv[4] = {v.x, v.y, v.z, v.w};
        unsigned short h[4], l[4];
#pragma unroll
        for (int j = 0; j < 4; j++) {
            __nv_bfloat16 hb = __float2bfloat16_rn(vv[j]);
            h[j] = __bfloat16_as_ushort(hb);
            __nv_bfloat16 lb = __float2bfloat16_rn(vv[j] - __bfloat162float(hb));
            l[j] = __bfloat16_as_ushort(lb);
        }
        uint2 ho = make_uint2((uint32_t)h[0] | ((uint32_t)h[1] << 16),
                              (uint32_t)h[2] | ((uint32_t)h[3] << 16));
        uint2 lz = make_uint2((uint32_t)l[0] | ((uint32_t)l[1] << 16),
                              (uint32_t)l[2] | ((uint32_t)l[3] << 16));
        *reinterpret_cast<uint2*>(hi + base) = ho;
        *reinterpret_cast<uint2*>(lo + base) = lz;
    }
}

// ---------------------------------------------------------------------------
// bf16x3 tensor-core GEMM:
//   C = Ahi*Bhi + Alo*Bhi + Ahi*Blo  (+ bias), fp32 accumulate.
// Block tile BM x 128, BK = 32 bf16, 8 warps (2x4), warp tile (BM/2) x 32.
// mma.sync.aligned.m16n8k16.row.col.f32.bf16.bf16.f32
// ---------------------------------------------------------------------------
__device__ __forceinline__ void mma_bf16(float* c, const uint32_t* a, const uint32_t* b) {
    asm volatile(
        "mma.sync.aligned.m16n8k16.row.col.f32.bf16.bf16.f32 "
        "{%0,%1,%2,%3}, {%4,%5,%6,%7}, {%8,%9}, {%0,%1,%2,%3};\n"
        : "+f"(c[0]), "+f"(c[1]), "+f"(c[2]), "+f"(c[3])
        : "r"(a[0]), "r"(a[1]), "r"(a[2]), "r"(a[3]), "r"(b[0]), "r"(b[1]));
}

template <int BM>
__global__ void __launch_bounds__(256)
gemm_bf16x3_kernel(const __nv_bfloat16* __restrict__ Ahi,
                   const __nv_bfloat16* __restrict__ Alo,
                   const __nv_bfloat16* __restrict__ Bhi,
                   const __nv_bfloat16* __restrict__ Blo,
                   float* __restrict__ C, const float* __restrict__ bias,
                   int M, int N, int K) {
    constexpr int BN = 128, BK = 32;
    constexpr int SA = BK / 2 + 4;   // u32 stride per A row (k-pairs + pad) = 20
    constexpr int SB = BN + 8;       // u32 stride per B pair-row = 136
    constexpr int WM = BM / 2, WN = BN / 4;
    constexpr int MT = WM / 16, NT = WN / 8;
    constexpr int AIT = BM / 64;

    __shared__ uint32_t As[2][BM * SA];
    __shared__ uint32_t Bs[2][16 * SB];

    const int tid  = threadIdx.x;
    const int lane = tid & 31, wid = tid >> 5;
    const int gid  = lane >> 2, tig = lane & 3;
    const int wm   = wid >> 2,  wn  = wid & 3;
    const int bm   = blockIdx.y * BM, bn = blockIdx.x * BN;

    const int KT = K / BK, T = 3 * KT;

    float acc[MT][NT][4];
#pragma unroll
    for (int i = 0; i < MT; i++)
#pragma unroll
        for (int j = 0; j < NT; j++)
#pragma unroll
            for (int q = 0; q < 4; q++) acc[i][j][q] = 0.0f;

    uint4 ar[AIT];
    uint2 bl[2], bh[2];

#define GLOAD(t)                                                                \
    {                                                                           \
        int seg = (t) / KT, kt = (t) % KT;                                      \
        const __nv_bfloat16* Ap = (seg == 1) ? Alo : Ahi;                       \
        const __nv_bfloat16* Bp = (seg == 2) ? Blo : Bhi;                       \
        int kb = kt * BK;                                                       \
        _Pragma("unroll")                                                       \
        for (int i = 0; i < AIT; i++)                                           \
            ar[i] = *reinterpret_cast<const uint4*>(                            \
                Ap + (size_t)(bm + (tid >> 2) + i * 64) * K + kb + (tid & 3) * 8); \
        _Pragma("unroll")                                                       \
        for (int i = 0; i < 2; i++) {                                           \
            int pr = wid + i * 8;                                               \
            const __nv_bfloat16* bb = Bp + (size_t)(kb + 2 * pr) * N + bn + lane * 4; \
            bl[i] = *reinterpret_cast<const uint2*>(bb);                        \
            bh[i] = *reinterpret_cast<const uint2*>(bb + N);                    \
        }                                                                       \
    }

#define SSTORE(bf)                                                              \
    {                                                                           \
        _Pragma("unroll")                                                       \
        for (int i = 0; i < AIT; i++)                                           \
            *reinterpret_cast<uint4*>(                                          \
                &As[bf][((tid >> 2) + i * 64) * SA + (tid & 3) * 4]) = ar[i];   \
        _Pragma("unroll")                                                       \
        for (int i = 0; i < 2; i++) {                                           \
            uint4 o;                                                            \
            o.x = __byte_perm(bl[i].x, bh[i].x, 0x5410);                        \
            o.y = __byte_perm(bl[i].x, bh[i].x, 0x7632);                        \
            o.z = __byte_perm(bl[i].y, bh[i].y, 0x5410);                        \
            o.w = __byte_perm(bl[i].y, bh[i].y, 0x7632);                        \
            *reinterpret_cast<uint4*>(&Bs[bf][(wid + i * 8) * SB + lane * 4]) = o; \
        }                                                                       \
    }

#define COMPUTE(bf)                                                             \
    {                                                                           \
        _Pragma("unroll")                                                       \
        for (int ks = 0; ks < 2; ks++) {                                        \
            uint32_t a[MT][4], b[NT][2];                                        \
            _Pragma("unroll")                                                   \
            for (int mt = 0; mt < MT; mt++) {                                   \
                int m = wm * WM + mt * 16 + gid;                                \
                const uint32_t* r0 = &As[bf][m * SA + ks * 8 + tig];            \
                a[mt][0] = r0[0];                                               \
                a[mt][2] = r0[4];                                               \
                const uint32_t* r1 = r0 + 8 * SA;                               \
                a[mt][1] = r1[0];                                               \
                a[mt][3] = r1[4];                                               \
            }                                                                   \
            _Pragma("unroll")                                                   \
            for (int nt = 0; nt < NT; nt++) {                                   \
                int n = wn * WN + nt * 8 + gid;                                 \
                const uint32_t* cb = &Bs[bf][(ks * 8 + tig) * SB + n];          \
                b[nt][0] = cb[0];                                               \
                b[nt][1] = cb[4 * SB];                                          \
            }                                                                   \
            _Pragma("unroll")                                                   \
            for (int mt = 0; mt < MT; mt++)                                     \
                _Pragma("unroll")                                               \
                for (int nt = 0; nt < NT; nt++)                                 \
                    mma_bf16(acc[mt][nt], a[mt], b[nt]);                        \
        }                                                                       \
    }

    GLOAD(0);
    SSTORE(0);
    __syncthreads();
    int buf = 0;
    for (int t = 0; t < T; t++) {
        if (t + 1 < T) GLOAD(t + 1);
        COMPUTE(buf);
        if (t + 1 < T) {
            SSTORE(buf ^ 1);
            __syncthreads();
            buf ^= 1;
        }
    }

#undef GLOAD
#undef SSTORE
#undef COMPUTE

#pragma unroll
    for (int mt = 0; mt < MT; mt++) {
#pragma unroll
        for (int nt = 0; nt < NT; nt++) {
            int m = bm + wm * WM + mt * 16 + gid;
            int n = bn + wn * WN + nt * 8 + 2 * tig;
            float b0 = bias ? bias[n] : 0.0f;
            float b1 = bias ? bias[n + 1] : 0.0f;
            float2 v0 = make_float2(acc[mt][nt][0] + b0, acc[mt][nt][1] + b1);
            float2 v1 = make_float2(acc[mt][nt][2] + b0, acc[mt][nt][3] + b1);
            *reinterpret_cast<float2*>(&C[(size_t)m * N + n]) = v0;
            *reinterpret_cast<float2*>(&C[(size_t)(m + 8) * N + n]) = v1;
        }
    }
}

// ---------------------------------------------------------------------------
// Attention: one block (256 thr = 8 warps) per query; warp w -> head w.
// Window = BOS + 125 stencil neighbors (5x5x5 over 2x32x32, causal nidx<=qi).
// ---------------------------------------------------------------------------
__device__ __forceinline__ float warpSum(float v) {
#pragma unroll
    for (int o = 16; o > 0; o >>= 1) v += __shfl_xor_sync(0xffffffffu, v, o);
    return v;
}
__device__ __forceinline__ float warpMax(float v) {
#pragma unroll
    for (int o = 16; o > 0; o >>= 1) v = fmaxf(v, __shfl_xor_sync(0xffffffffu, v, o));
    return v;
}

__global__ void __launch_bounds__(256)
attn_kernel(const float* __restrict__ qkv, float* __restrict__ out) {
    const int bid = blockIdx.x;
    const int tid = threadIdx.x;

    if (bid == 2047) {
        for (int c = tid; c < INNER; c += blockDim.x) out[c] = qkv[2 * INNER + c];
        return;
    }

    const int qi   = bid;
    const int h    = tid >> 5;
    const int lane = tid & 31;

    const float scale = 0.125f;
    const float* qrow = qkv + (size_t)(qi + 1) * QKVW + h * DHEAD;
    const float q0 = qrow[lane] * scale;
    const float q1 = qrow[lane + 32] * scale;

    const int f  = qi >> 10;
    const int yy = (qi >> 5) & 31;
    const int xx = qi & 31;

    const float* kbase = qkv + INNER + h * DHEAD;
    const float* vbase = qkv + 2 * INNER + h * DHEAD;

    float s[4] = {-FLT_MAX, -FLT_MAX, -FLT_MAX, -FLT_MAX};

    {
        float part = q0 * kbase[lane] + q1 * kbase[lane + 32];
        float val = warpSum(part);
        if (lane == 0) s[0] = val;
    }

#pragma unroll 5
    for (int jj = 0; jj < 125; jj++) {
        const int j  = jj + 1;
        const int df = jj / 25 - 2;
        const int dh = (jj / 5) % 5 - 2;
        const int dw = jj % 5 - 2;
        const int nf = f + df, nh = yy + dh, nw = xx + dw;
        bool valid = ((unsigned)nf < 2u) & ((unsigned)nh < 32u) & ((unsigned)nw < 32u);
        const int nidx = (nf << 10) + (nh << 5) + nw;
        valid = valid && (nidx <= qi);
        if (valid) {
            const float* kr = kbase + (size_t)(nidx + 1) * QKVW;
            float part = q0 * kr[lane] + q1 * kr[lane + 32];
            float val = warpSum(part);
            if (lane == (j & 31)) s[j >> 5] = val;
        }
    }

    float m = fmaxf(fmaxf(s[0], s[1]), fmaxf(s[2], s[3]));
    m = warpMax(m);
    float z = 0.0f;
#pragma unroll
    for (int t = 0; t < 4; t++) {
        s[t] = __expf(s[t] - m);
        z += s[t];
    }
    z = warpSum(z);
    const float invz = 1.0f / z;
#pragma unroll
    for (int t = 0; t < 4; t++) s[t] *= invz;

    float a0, a1;
    {
        float p = __shfl_sync(0xffffffffu, s[0], 0);
        a0 = p * vbase[lane];
        a1 = p * vbase[lane + 32];
    }

#pragma unroll 5
    for (int jj = 0; jj < 125; jj++) {
        const int j  = jj + 1;
        const int df = jj / 25 - 2;
        const int dh = (jj / 5) % 5 - 2;
        const int dw = jj % 5 - 2;
        const int nf = f + df, nh = yy + dh, nw = xx + dw;
        bool valid = ((unsigned)nf < 2u) & ((unsigned)nh < 32u) & ((unsigned)nw < 32u);
        const int nidx = (nf << 10) + (nh << 5) + nw;
        valid = valid && (nidx <= qi);
        if (valid) {
            float p = __shfl_sync(0xffffffffu, s[j >> 5], j & 31);
            const float* vr = vbase + (size_t)(nidx + 1) * QKVW;
            a0 = fmaf(p, vr[lane], a0);
            a1 = fmaf(p, vr[lane + 32], a1);
        }
    }

    float* orow = out + (size_t)(qi + 1) * INNER + h * DHEAD;
    orow[lane] = a0;
    orow[lane + 32] = a1;
}

// ---------------------------------------------------------------------------
extern "C" void kernel_launch(void* const* d_in, const int* in_sizes, int n_in,
                              void* d_out, int out_size) {
    const float* x     = (const float*)d_in[0];  // (1, 2048, 512)
    const float* w_qkv = (const float*)d_in[1];  // (512, 1536)
    const float* w_out = (const float*)d_in[2];  // (512, 512)
    const float* b_out = (const float*)d_in[3];  // (512,)
    float* out = (float*)d_out;

    float *qkv, *attn;
    __nv_bfloat16 *xhi, *xlo, *w1hi, *w1lo, *ahi, *alo, *w2hi, *w2lo;
    cudaGetSymbolAddress((void**)&qkv,  g_qkv);
    cudaGetSymbolAddress((void**)&attn, g_attn);
    cudaGetSymbolAddress((void**)&xhi,  g_xhi);
    cudaGetSymbolAddress((void**)&xlo,  g_xlo);
    cudaGetSymbolAddress((void**)&w1hi, g_w1hi);
    cudaGetSymbolAddress((void**)&w1lo, g_w1lo);
    cudaGetSymbolAddress((void**)&ahi,  g_ahi);
    cudaGetSymbolAddress((void**)&alo,  g_alo);
    cudaGetSymbolAddress((void**)&w2hi, g_w2hi);
    cudaGetSymbolAddress((void**)&w2lo, g_w2lo);

    auto splitLaunch = [&](const float* src, __nv_bfloat16* h, __nv_bfloat16* l, int n) {
        int quads = n / 4;
        split_bf16_kernel<<<(quads + 255) / 256, 256>>>(src, h, l, n);
    };

    // Split inputs to (hi, lo) bf16
    splitLaunch(x,     xhi,  xlo,  NTOK * INNER);
    splitLaunch(w_qkv, w1hi, w1lo, INNER * QKVW);
    splitLaunch(w_out, w2hi, w2lo, INNER * INNER);

    // 1) qkv = x @ w_qkv  (bf16x3 tensor-core GEMM)
    gemm_bf16x3_kernel<128><<<dim3(QKVW / 128, NTOK / 128), 256>>>(
        xhi, xlo, w1hi, w1lo, qkv, nullptr, NTOK, QKVW, INNER);

    // 2) windowed causal attention
    attn_kernel<<<2048, 256>>>(qkv, attn);

    // 3) split attention output, then out = attn @ w_out + b_out
    splitLaunch(attn, ahi, alo, NTOK * INNER);
    gemm_bf16x3_kernel<64><<<dim3(INNER / 128, NTOK / 64), 256>>>(
        ahi, alo, w2hi, w2lo, out, b_out, NTOK, INNER, INNER);
}

// round 4
// speedup vs baseline: 1.7637x; 1.2431x over previous
#include <cuda_runtime.h>
#include <cuda_bf16.h>
#include <cstdint>
#include <float.h>
#include <math.h>

// Problem constants
#define NTOK   2048          // N = F*H*W = 2*32*32
#define INNER  512
#define QKVW   1536          // 3*INNER
#define HEADS  8
#define DHEAD  64

// Scratch (device globals; no allocation allowed)
__device__ float g_qkv[NTOK * QKVW];
__device__ __nv_bfloat16 g_xhi[NTOK * INNER],  g_xlo[NTOK * INNER];
__device__ __nv_bfloat16 g_w1hi[INNER * QKVW], g_w1lo[INNER * QKVW];
__device__ __nv_bfloat16 g_ahi[NTOK * INNER],  g_alo[NTOK * INNER];
__device__ __nv_bfloat16 g_w2hi[INNER * INNER], g_w2lo[INNER * INNER];

// ---------------------------------------------------------------------------
// Split fp32 -> (hi, lo) bf16 pair:  hi = bf16(v), lo = bf16(v - hi)
// ---------------------------------------------------------------------------
__global__ void __launch_bounds__(256)
split_bf16_kernel(const float* __restrict__ in,
                  __nv_bfloat16* __restrict__ hi,
                  __nv_bfloat16* __restrict__ lo, int n) {
    int base = (blockIdx.x * 256 + threadIdx.x) * 4;
    if (base < n) {
        float4 v = *reinterpret_cast<const float4*>(in + base);
        float vv[4] = {v.x, v.y, v.z, v.w};
        unsigned short h[4], l[4];
#pragma unroll
        for (int j = 0; j < 4; j++) {
            __nv_bfloat16 hb = __float2bfloat16_rn(vv[j]);
            h[j] = __bfloat16_as_ushort(hb);
            __nv_bfloat16 lb = __float2bfloat16_rn(vv[j] - __bfloat162float(hb));
            l[j] = __bfloat16_as_ushort(lb);
        }
        uint2 ho = make_uint2((uint32_t)h[0] | ((uint32_t)h[1] << 16),
                              (uint32_t)h[2] | ((uint32_t)h[3] << 16));
        uint2 lz = make_uint2((uint32_t)l[0] | ((uint32_t)l[1] << 16),
                              (uint32_t)l[2] | ((uint32_t)l[3] << 16));
        *reinterpret_cast<uint2*>(hi + base) = ho;
        *reinterpret_cast<uint2*>(lo + base) = lz;
    }
}

// ---------------------------------------------------------------------------
// bf16x3 tensor-core GEMM (unchanged from round 3)
// ---------------------------------------------------------------------------
__device__ __forceinline__ void mma_bf16(float* c, const uint32_t* a, const uint32_t* b) {
    asm volatile(
        "mma.sync.aligned.m16n8k16.row.col.f32.bf16.bf16.f32 "
        "{%0,%1,%2,%3}, {%4,%5,%6,%7}, {%8,%9}, {%0,%1,%2,%3};\n"
        : "+f"(c[0]), "+f"(c[1]), "+f"(c[2]), "+f"(c[3])
        : "r"(a[0]), "r"(a[1]), "r"(a[2]), "r"(a[3]), "r"(b[0]), "r"(b[1]));
}

template <int BM>
__global__ void __launch_bounds__(256)
gemm_bf16x3_kernel(const __nv_bfloat16* __restrict__ Ahi,
                   const __nv_bfloat16* __restrict__ Alo,
                   const __nv_bfloat16* __restrict__ Bhi,
                   const __nv_bfloat16* __restrict__ Blo,
                   float* __restrict__ C, const float* __restrict__ bias,
                   int M, int N, int K) {
    constexpr int BN = 128, BK = 32;
    constexpr int SA = BK / 2 + 4;   // u32 stride per A row = 20
    constexpr int SB = BN + 8;       // u32 stride per B pair-row = 136
    constexpr int WM = BM / 2, WN = BN / 4;
    constexpr int MT = WM / 16, NT = WN / 8;
    constexpr int AIT = BM / 64;

    __shared__ uint32_t As[2][BM * SA];
    __shared__ uint32_t Bs[2][16 * SB];

    const int tid  = threadIdx.x;
    const int lane = tid & 31, wid = tid >> 5;
    const int gid  = lane >> 2, tig = lane & 3;
    const int wm   = wid >> 2,  wn  = wid & 3;
    const int bm   = blockIdx.y * BM, bn = blockIdx.x * BN;

    const int KT = K / BK, T = 3 * KT;

    float acc[MT][NT][4];
#pragma unroll
    for (int i = 0; i < MT; i++)
#pragma unroll
        for (int j = 0; j < NT; j++)
#pragma unroll
            for (int q = 0; q < 4; q++) acc[i][j][q] = 0.0f;

    uint4 ar[AIT];
    uint2 bl[2], bh[2];

#define GLOAD(t)                                                                \
    {                                                                           \
        int seg = (t) / KT, kt = (t) % KT;                                      \
        const __nv_bfloat16* Ap = (seg == 1) ? Alo : Ahi;                       \
        const __nv_bfloat16* Bp = (seg == 2) ? Blo : Bhi;                       \
        int kb = kt * BK;                                                       \
        _Pragma("unroll")                                                       \
        for (int i = 0; i < AIT; i++)                                           \
            ar[i] = *reinterpret_cast<const uint4*>(                            \
                Ap + (size_t)(bm + (tid >> 2) + i * 64) * K + kb + (tid & 3) * 8); \
        _Pragma("unroll")                                                       \
        for (int i = 0; i < 2; i++) {                                           \
            int pr = wid + i * 8;                                               \
            const __nv_bfloat16* bb = Bp + (size_t)(kb + 2 * pr) * N + bn + lane * 4; \
            bl[i] = *reinterpret_cast<const uint2*>(bb);                        \
            bh[i] = *reinterpret_cast<const uint2*>(bb + N);                    \
        }                                                                       \
    }

#define SSTORE(bf)                                                              \
    {                                                                           \
        _Pragma("unroll")                                                       \
        for (int i = 0; i < AIT; i++)                                           \
            *reinterpret_cast<uint4*>(                                          \
                &As[bf][((tid >> 2) + i * 64) * SA + (tid & 3) * 4]) = ar[i];   \
        _Pragma("unroll")                                                       \
        for (int i = 0; i < 2; i++) {                                           \
            uint4 o;                                                            \
            o.x = __byte_perm(bl[i].x, bh[i].x, 0x5410);                        \
            o.y = __byte_perm(bl[i].x, bh[i].x, 0x7632);                        \
            o.z = __byte_perm(bl[i].y, bh[i].y, 0x5410);                        \
            o.w = __byte_perm(bl[i].y, bh[i].y, 0x7632);                        \
            *reinterpret_cast<uint4*>(&Bs[bf][(wid + i * 8) * SB + lane * 4]) = o; \
        }                                                                       \
    }

#define COMPUTE(bf)                                                             \
    {                                                                           \
        _Pragma("unroll")                                                       \
        for (int ks = 0; ks < 2; ks++) {                                        \
            uint32_t a[MT][4], b[NT][2];                                        \
            _Pragma("unroll")                                                   \
            for (int mt = 0; mt < MT; mt++) {                                   \
                int m = wm * WM + mt * 16 + gid;                                \
                const uint32_t* r0 = &As[bf][m * SA + ks * 8 + tig];            \
                a[mt][0] = r0[0];                                               \
                a[mt][2] = r0[4];                                               \
                const uint32_t* r1 = r0 + 8 * SA;                               \
                a[mt][1] = r1[0];                                               \
                a[mt][3] = r1[4];                                               \
            }                                                                   \
            _Pragma("unroll")                                                   \
            for (int nt = 0; nt < NT; nt++) {                                   \
                int n = wn * WN + nt * 8 + gid;                                 \
                const uint32_t* cb = &Bs[bf][(ks * 8 + tig) * SB + n];          \
                b[nt][0] = cb[0];                                               \
                b[nt][1] = cb[4 * SB];                                          \
            }                                                                   \
            _Pragma("unroll")                                                   \
            for (int mt = 0; mt < MT; mt++)                                     \
                _Pragma("unroll")                                               \
                for (int nt = 0; nt < NT; nt++)                                 \
                    mma_bf16(acc[mt][nt], a[mt], b[nt]);                        \
        }                                                                       \
    }

    GLOAD(0);
    SSTORE(0);
    __syncthreads();
    int buf = 0;
    for (int t = 0; t < T; t++) {
        if (t + 1 < T) GLOAD(t + 1);
        COMPUTE(buf);
        if (t + 1 < T) {
            SSTORE(buf ^ 1);
            __syncthreads();
            buf ^= 1;
        }
    }

#undef GLOAD
#undef SSTORE
#undef COMPUTE

#pragma unroll
    for (int mt = 0; mt < MT; mt++) {
#pragma unroll
        for (int nt = 0; nt < NT; nt++) {
            int m = bm + wm * WM + mt * 16 + gid;
            int n = bn + wn * WN + nt * 8 + 2 * tig;
            float b0 = bias ? bias[n] : 0.0f;
            float b1 = bias ? bias[n + 1] : 0.0f;
            float2 v0 = make_float2(acc[mt][nt][0] + b0, acc[mt][nt][1] + b1);
            float2 v1 = make_float2(acc[mt][nt][2] + b0, acc[mt][nt][3] + b1);
            *reinterpret_cast<float2*>(&C[(size_t)m * N + n]) = v0;
            *reinterpret_cast<float2*>(&C[(size_t)(m + 8) * N + n]) = v1;
        }
    }
}

// ---------------------------------------------------------------------------
// Attention v2: block per query, warp = head. Within a warp, 4 groups of
// 8 lanes; each group computes one window slot's full 64-dim dot via
// 2x LDG.128/lane + 8 FMA + 3 shfl. Sims/probs staged in smem.
// Epilogue writes bf16 (hi, lo) pair directly for GEMM2.
// ---------------------------------------------------------------------------
__device__ __forceinline__ float warpSum(float v) {
#pragma unroll
    for (int o = 16; o > 0; o >>= 1) v += __shfl_xor_sync(0xffffffffu, v, o);
    return v;
}
__device__ __forceinline__ float warpMax(float v) {
#pragma unroll
    for (int o = 16; o > 0; o >>= 1) v = fmaxf(v, __shfl_xor_sync(0xffffffffu, v, o));
    return v;
}

__device__ __forceinline__ void pack_hilo(float4 v, uint2& hi, uint2& lo) {
    unsigned short h[4], l[4];
    float vv[4] = {v.x, v.y, v.z, v.w};
#pragma unroll
    for (int j = 0; j < 4; j++) {
        __nv_bfloat16 hb = __float2bfloat16_rn(vv[j]);
        h[j] = __bfloat16_as_ushort(hb);
        l[j] = __bfloat16_as_ushort(__float2bfloat16_rn(vv[j] - __bfloat162float(hb)));
    }
    hi = make_uint2((uint32_t)h[0] | ((uint32_t)h[1] << 16),
                    (uint32_t)h[2] | ((uint32_t)h[3] << 16));
    lo = make_uint2((uint32_t)l[0] | ((uint32_t)l[1] << 16),
                    (uint32_t)l[2] | ((uint32_t)l[3] << 16));
}

__global__ void __launch_bounds__(256)
attn_kernel(const float* __restrict__ qkv,
            __nv_bfloat16* __restrict__ ahi, __nv_bfloat16* __restrict__ alo) {
    __shared__ float sims[HEADS][128];
    __shared__ int   rows[HEADS][128];

    const int bid = blockIdx.x;
    const int tid = threadIdx.x;

    if (bid == 2047) {
        // out row 0 = v_bos = qkv[0, 1024:1536], split to bf16 hi/lo
        for (int c = tid; c < INNER; c += 256) {
            float v = qkv[2 * INNER + c];
            __nv_bfloat16 hb = __float2bfloat16_rn(v);
            ahi[c] = hb;
            alo[c] = __float2bfloat16_rn(v - __bfloat162float(hb));
        }
        return;
    }

    const int qi   = bid;          // query 0..2046 (xp pos qi+1)
    const int h    = tid >> 5;
    const int lane = tid & 31;
    const int g    = lane >> 3;    // group 0..3
    const int li   = lane & 7;     // lane in group

    // q fragment: dims [li*4, li*4+3] and [32+li*4, ...]
    const float* qrow = qkv + (size_t)(qi + 1) * QKVW + h * DHEAD;
    float4 q4a = *reinterpret_cast<const float4*>(qrow + li * 4);
    float4 q4b = *reinterpret_cast<const float4*>(qrow + 32 + li * 4);
    const float sc = 0.125f;
    q4a.x *= sc; q4a.y *= sc; q4a.z *= sc; q4a.w *= sc;
    q4b.x *= sc; q4b.y *= sc; q4b.z *= sc; q4b.w *= sc;

    const int f  = qi >> 10;
    const int yy = (qi >> 5) & 31;
    const int xx = qi & 31;

    const float* kbase = qkv + INNER;
    const float* vbase = qkv + 2 * INNER;

    // ---- phase 1: sims for slots 0..125 (slot 0 = BOS) ----
#pragma unroll 4
    for (int it = 0; it < 32; it++) {
        const int s = it * 4 + g;
        int row = 0;
        bool valid;
        if (s == 0) {
            valid = true;
        } else {
            const int jj = s - 1;
            const int df = jj / 25;
            const int rem = jj - df * 25;
            const int dh = rem / 5;
            const int dw = rem - dh * 5;
            const int nf = f + df - 2, nh = yy + dh - 2, nw = xx + dw - 2;
            valid = (jj < 125) & ((unsigned)nf < 2u) & ((unsigned)nh < 32u) &
                    ((unsigned)nw < 32u);
            const int nidx = (nf << 10) + (nh << 5) + nw;
            valid = valid && (nidx <= qi);
            row = nidx + 1;
        }
        float part = 0.0f;
        if (valid) {
            const float* kr = kbase + (size_t)row * QKVW + h * DHEAD;
            float4 k4a = *reinterpret_cast<const float4*>(kr + li * 4);
            float4 k4b = *reinterpret_cast<const float4*>(kr + 32 + li * 4);
            part = q4a.x * k4a.x + q4a.y * k4a.y + q4a.z * k4a.z + q4a.w * k4a.w +
                   q4b.x * k4b.x + q4b.y * k4b.y + q4b.z * k4b.z + q4b.w * k4b.w;
        }
        part += __shfl_xor_sync(0xffffffffu, part, 1);
        part += __shfl_xor_sync(0xffffffffu, part, 2);
        part += __shfl_xor_sync(0xffffffffu, part, 4);
        if (li == 0) {
            sims[h][s] = valid ? part : -FLT_MAX;
            rows[h][s] = row;
        }
    }
    __syncwarp();

    // ---- softmax over 126 slots (lane owns slots lane+32t) ----
    float sv[4];
#pragma unroll
    for (int t = 0; t < 4; t++) {
        const int s = lane + 32 * t;
        sv[t] = (s < 126) ? sims[h][s] : -FLT_MAX;
    }
    float m = fmaxf(fmaxf(sv[0], sv[1]), fmaxf(sv[2], sv[3]));
    m = warpMax(m);
    float z = 0.0f;
#pragma unroll
    for (int t = 0; t < 4; t++) {
        sv[t] = __expf(sv[t] - m);
        z += sv[t];
    }
    z = warpSum(z);
    const float invz = 1.0f / z;
#pragma unroll
    for (int t = 0; t < 4; t++) {
        const int s = lane + 32 * t;
        if (s < 126) sims[h][s] = sv[t] * invz;
    }
    __syncwarp();

    // ---- phase 2: PV accumulation ----
    float4 aa = make_float4(0.f, 0.f, 0.f, 0.f);
    float4 ab = make_float4(0.f, 0.f, 0.f, 0.f);
#pragma unroll 4
    for (int it = 0; it < 32; it++) {
        const int s = it * 4 + g;
        if (s < 126) {
            const float p = sims[h][s];
            if (p != 0.0f) {      // masked slots have exactly p == 0
                const int row = rows[h][s];
                const float* vr = vbase + (size_t)row * QKVW + h * DHEAD;
                float4 v4a = *reinterpret_cast<const float4*>(vr + li * 4);
                float4 v4b = *reinterpret_cast<const float4*>(vr + 32 + li * 4);
                aa.x = fmaf(p, v4a.x, aa.x); aa.y = fmaf(p, v4a.y, aa.y);
                aa.z = fmaf(p, v4a.z, aa.z); aa.w = fmaf(p, v4a.w, aa.w);
                ab.x = fmaf(p, v4b.x, ab.x); ab.y = fmaf(p, v4b.y, ab.y);
                ab.z = fmaf(p, v4b.z, ab.z); ab.w = fmaf(p, v4b.w, ab.w);
            }
        }
    }

    // cross-group reduce (groups hold disjoint slot subsets of same dims)
#pragma unroll
    for (int off = 8; off <= 16; off <<= 1) {
        aa.x += __shfl_xor_sync(0xffffffffu, aa.x, off);
        aa.y += __shfl_xor_sync(0xffffffffu, aa.y, off);
        aa.z += __shfl_xor_sync(0xffffffffu, aa.z, off);
        aa.w += __shfl_xor_sync(0xffffffffu, aa.w, off);
        ab.x += __shfl_xor_sync(0xffffffffu, ab.x, off);
        ab.y += __shfl_xor_sync(0xffffffffu, ab.y, off);
        ab.z += __shfl_xor_sync(0xffffffffu, ab.z, off);
        ab.w += __shfl_xor_sync(0xffffffffu, ab.w, off);
    }

    if (g == 0) {
        const size_t obase = (size_t)(qi + 1) * INNER + h * DHEAD;
        uint2 hi, lo;
        pack_hilo(aa, hi, lo);
        *reinterpret_cast<uint2*>(ahi + obase + li * 4) = hi;
        *reinterpret_cast<uint2*>(alo + obase + li * 4) = lo;
        pack_hilo(ab, hi, lo);
        *reinterpret_cast<uint2*>(ahi + obase + 32 + li * 4) = hi;
        *reinterpret_cast<uint2*>(alo + obase + 32 + li * 4) = lo;
    }
}

// ---------------------------------------------------------------------------
extern "C" void kernel_launch(void* const* d_in, const int* in_sizes, int n_in,
                              void* d_out, int out_size) {
    const float* x     = (const float*)d_in[0];  // (1, 2048, 512)
    const float* w_qkv = (const float*)d_in[1];  // (512, 1536)
    const float* w_out = (const float*)d_in[2];  // (512, 512)
    const float* b_out = (const float*)d_in[3];  // (512,)
    float* out = (float*)d_out;

    float* qkv;
    __nv_bfloat16 *xhi, *xlo, *w1hi, *w1lo, *ahi, *alo, *w2hi, *w2lo;
    cudaGetSymbolAddress((void**)&qkv,  g_qkv);
    cudaGetSymbolAddress((void**)&xhi,  g_xhi);
    cudaGetSymbolAddress((void**)&xlo,  g_xlo);
    cudaGetSymbolAddress((void**)&w1hi, g_w1hi);
    cudaGetSymbolAddress((void**)&w1lo, g_w1lo);
    cudaGetSymbolAddress((void**)&ahi,  g_ahi);
    cudaGetSymbolAddress((void**)&alo,  g_alo);
    cudaGetSymbolAddress((void**)&w2hi, g_w2hi);
    cudaGetSymbolAddress((void**)&w2lo, g_w2lo);

    auto splitLaunch = [&](const float* src, __nv_bfloat16* h, __nv_bfloat16* l, int n) {
        int quads = n / 4;
        split_bf16_kernel<<<(quads + 255) / 256, 256>>>(src, h, l, n);
    };

    // Split inputs to (hi, lo) bf16
    splitLaunch(x,     xhi,  xlo,  NTOK * INNER);
    splitLaunch(w_qkv, w1hi, w1lo, INNER * QKVW);
    splitLaunch(w_out, w2hi, w2lo, INNER * INNER);

    // 1) qkv = x @ w_qkv  (bf16x3 tensor-core GEMM)
    gemm_bf16x3_kernel<128><<<dim3(QKVW / 128, NTOK / 128), 256>>>(
        xhi, xlo, w1hi, w1lo, qkv, nullptr, NTOK, QKVW, INNER);

    // 2) windowed causal attention (writes bf16 hi/lo directly)
    attn_kernel<<<2048, 256>>>(qkv, ahi, alo);

    // 3) out = attn @ w_out + b_out
    gemm_bf16x3_kernel<64><<<dim3(INNER / 128, NTOK / 64), 256>>>(
        ahi, alo, w2hi, w2lo, out, b_out, NTOK, INNER, INNER);
}

// round 6
// speedup vs baseline: 1.7986x; 1.0198x over previous
#include <cuda_runtime.h>
#include <cuda_bf16.h>
#include <cstdint>
#include <float.h>
#include <math.h>

// Problem constants
#define NTOK   2048          // N = F*H*W = 2*32*32
#define INNER  512
#define QKVW   1536          // 3*INNER
#define HEADS  8
#define DHEAD  64
#define KDIM   512           // GEMM K for both GEMMs

// Scratch (device globals; no allocation allowed)
__device__ float g_qkv[NTOK * QKVW];
__device__ __nv_bfloat16 g_xhi[NTOK * INNER],    g_xlo[NTOK * INNER];
__device__ __nv_bfloat16 g_w1hiT[QKVW * INNER],  g_w1loT[QKVW * INNER];   // [N,K]
__device__ __nv_bfloat16 g_ahi[NTOK * INNER],    g_alo[NTOK * INNER];
__device__ __nv_bfloat16 g_w2hiT[INNER * INNER], g_w2loT[INNER * INNER];  // [N,K]

// ---------------------------------------------------------------------------
// Split fp32 -> (hi, lo) bf16, same layout
// ---------------------------------------------------------------------------
__global__ void __launch_bounds__(256)
split_bf16_kernel(const float* __restrict__ in,
                  __nv_bfloat16* __restrict__ hi,
                  __nv_bfloat16* __restrict__ lo, int n) {
    int base = (blockIdx.x * 256 + threadIdx.x) * 4;
    if (base < n) {
        float4 v = *reinterpret_cast<const float4*>(in + base);
        float vv[4] = {v.x, v.y, v.z, v.w};
        unsigned short h[4], l[4];
#pragma unroll
        for (int j = 0; j < 4; j++) {
            __nv_bfloat16 hb = __float2bfloat16_rn(vv[j]);
            h[j] = __bfloat16_as_ushort(hb);
            l[j] = __bfloat16_as_ushort(__float2bfloat16_rn(vv[j] - __bfloat162float(hb)));
        }
        uint2 ho = make_uint2((uint32_t)h[0] | ((uint32_t)h[1] << 16),
                              (uint32_t)h[2] | ((uint32_t)h[3] << 16));
        uint2 lz = make_uint2((uint32_t)l[0] | ((uint32_t)l[1] << 16),
                              (uint32_t)l[2] | ((uint32_t)l[3] << 16));
        *reinterpret_cast<uint2*>(hi + base) = ho;
        *reinterpret_cast<uint2*>(lo + base) = lz;
    }
}

// ---------------------------------------------------------------------------
// Transpose + split: in [K, N] fp32 -> hiT/loT [N, K] bf16
// ---------------------------------------------------------------------------
__global__ void __launch_bounds__(256)
tsplit_kernel(const float* __restrict__ in, __nv_bfloat16* __restrict__ hiT,
              __nv_bfloat16* __restrict__ loT, int K, int N) {
    __shared__ float sm[32][33];
    const int n0 = blockIdx.x * 32, k0 = blockIdx.y * 32;
    const int tx = threadIdx.x & 31, ty = threadIdx.x >> 5;
#pragma unroll
    for (int i = 0; i < 4; i++)
        sm[ty + i * 8][tx] = in[(size_t)(k0 + ty + i * 8) * N + n0 + tx];
    __syncthreads();
#pragma unroll
    for (int i = 0; i < 4; i++) {
        int nr = ty + i * 8;
        float v = sm[tx][nr];
        __nv_bfloat16 hb = __float2bfloat16_rn(v);
        hiT[(size_t)(n0 + nr) * K + k0 + tx] = hb;
        loT[(size_t)(n0 + nr) * K + k0 + tx] =
            __float2bfloat16_rn(v - __bfloat162float(hb));
    }
}

// ---------------------------------------------------------------------------
// bf16x3 mma.sync GEMM, cp.async 4-stage pipeline.
//   C[M,N] = Ahi*Bhi + Alo*Bhi + Ahi*Blo (+bias)
// A: [M, K=512] bf16 (hi/lo), B: [N, K=512] bf16 (hi/lo)  — both K-major.
// CTA tile 64 x BN, BK=32, 8 warps (2x4), warp tile 32 x (BN/4).
// smem rows padded to 20 u32 (80B) — conflict-free fragment LDS pattern.
// ---------------------------------------------------------------------------
__device__ __forceinline__ void mma_bf16(float* c, const uint32_t* a, const uint32_t* b) {
    asm volatile(
        "mma.sync.aligned.m16n8k16.row.col.f32.bf16.bf16.f32 "
        "{%0,%1,%2,%3}, {%4,%5,%6,%7}, {%8,%9}, {%0,%1,%2,%3};\n"
        : "+f"(c[0]), "+f"(c[1]), "+f"(c[2]), "+f"(c[3])
        : "r"(a[0]), "r"(a[1]), "r"(a[2]), "r"(a[3]), "r"(b[0]), "r"(b[1]));
}

__device__ __forceinline__ uint32_t smem_u32(const void* p) {
    uint32_t a;
    asm("{ .reg .u64 t; cvta.to.shared.u64 t, %1; cvt.u32.u64 %0, t; }"
        : "=r"(a) : "l"(p));
    return a;
}

template <int BN>
__global__ void __launch_bounds__(256, 3)
gemm_ca_kernel(const __nv_bfloat16* __restrict__ Ahi,
               const __nv_bfloat16* __restrict__ Alo,
               const __nv_bfloat16* __restrict__ Bhi,
               const __nv_bfloat16* __restrict__ Blo,
               float* __restrict__ C, const float* __restrict__ bias, int N) {
    constexpr int BM = 64, K = KDIM;
    constexpr int SA = 20;                       // u32 per smem row (32 bf16 + pad)
    constexpr int ABYTES = BM * SA * 4;          // 5120
    constexpr int BBYTES = BN * SA * 4;          // 10240 (BN=128) / 5120
    constexpr int STAGE  = ABYTES + BBYTES;
    constexpr int NCH    = 48;                   // 3 segments * 512/32
    constexpr int WN = BN / 4;
    constexpr int MT = 2, NT = WN / 8;
    constexpr int BCH = BN * 4 / 256;            // B 16B-chunks per thread

    extern __shared__ char dsm[];

    const int tid  = threadIdx.x;
    const int lane = tid & 31, wid = tid >> 5;
    const int gid  = lane >> 2, tig = lane & 3;
    const int wm   = wid >> 2,  wn  = wid & 3;
    const int bm   = blockIdx.y * BM, bn = blockIdx.x * BN;
    const uint32_t sbase = smem_u32(dsm);

    float acc[MT][NT][4];
#pragma unroll
    for (int i = 0; i < MT; i++)
#pragma unroll
        for (int j = 0; j < NT; j++)
#pragma unroll
            for (int q = 0; q < 4; q++) acc[i][j][q] = 0.0f;

#define PREFETCH(c)                                                            \
    {                                                                          \
        const int _s = (c) & 3;                                                \
        const int _seg = (c) >> 4;                                             \
        const int _kk = ((c) & 15) * 32;                                       \
        const __nv_bfloat16* _Ap = (_seg == 1) ? Alo : Ahi;                    \
        const __nv_bfloat16* _Bp = (_seg == 2) ? Blo : Bhi;                    \
        const uint32_t _ab = sbase + _s * STAGE;                               \
        const uint32_t _bb = _ab + ABYTES;                                     \
        {                                                                      \
            const int _r = tid >> 2, _ch = tid & 3;                            \
            asm volatile("cp.async.ca.shared.global [%0], [%1], 16;"           \
                :: "r"(_ab + _r * 80 + _ch * 16),                              \
                   "l"(_Ap + (size_t)(bm + _r) * K + _kk + _ch * 8));          \
        }                                                                      \
        _Pragma("unroll")                                                      \
        for (int _i = 0; _i < BCH; _i++) {                                     \
            const int _u = tid + _i * 256;                                     \
            const int _r = _u >> 2, _ch = _u & 3;                              \
            asm volatile("cp.async.ca.shared.global [%0], [%1], 16;"           \
                :: "r"(_bb + _r * 80 + _ch * 16),                              \
                   "l"(_Bp + (size_t)(bn + _r) * K + _kk + _ch * 8));          \
        }                                                                      \
    }

    PREFETCH(0); asm volatile("cp.async.commit_group;" ::: "memory");
    PREFETCH(1); asm volatile("cp.async.commit_group;" ::: "memory");
    PREFETCH(2); asm volatile("cp.async.commit_group;" ::: "memory");

    for (int c = 0; c < NCH; c++) {
        asm volatile("cp.async.wait_group 2;" ::: "memory");
        __syncthreads();

        const uint32_t* As = reinterpret_cast<const uint32_t*>(dsm + (c & 3) * STAGE);
        const uint32_t* Bs = reinterpret_cast<const uint32_t*>(dsm + (c & 3) * STAGE + ABYTES);

#pragma unroll
        for (int ks = 0; ks < 2; ks++) {
            uint32_t a[MT][4], b[NT][2];
#pragma unroll
            for (int mt = 0; mt < MT; mt++) {
                const int m = wm * 32 + mt * 16 + gid;
                const uint32_t* r0 = As + m * SA + ks * 8 + tig;
                a[mt][0] = r0[0];
                a[mt][2] = r0[4];
                const uint32_t* r1 = r0 + 8 * SA;
                a[mt][1] = r1[0];
                a[mt][3] = r1[4];
            }
#pragma unroll
            for (int nt = 0; nt < NT; nt++) {
                const int n = wn * WN + nt * 8 + gid;
                const uint32_t* br = Bs + n * SA + ks * 8 + tig;
                b[nt][0] = br[0];
                b[nt][1] = br[4];
            }
#pragma unroll
            for (int mt = 0; mt < MT; mt++)
#pragma unroll
                for (int nt = 0; nt < NT; nt++)
                    mma_bf16(acc[mt][nt], a[mt], b[nt]);
        }

        __syncthreads();
        if (c + 3 < NCH) PREFETCH(c + 3);
        asm volatile("cp.async.commit_group;" ::: "memory");
    }
#undef PREFETCH

#pragma unroll
    for (int mt = 0; mt < MT; mt++) {
#pragma unroll
        for (int nt = 0; nt < NT; nt++) {
            const int m = bm + wm * 32 + mt * 16 + gid;
            const int n = bn + wn * WN + nt * 8 + 2 * tig;
            float b0 = bias ? bias[n] : 0.0f;
            float b1 = bias ? bias[n + 1] : 0.0f;
            float2 v0 = make_float2(acc[mt][nt][0] + b0, acc[mt][nt][1] + b1);
            float2 v1 = make_float2(acc[mt][nt][2] + b0, acc[mt][nt][3] + b1);
            *reinterpret_cast<float2*>(&C[(size_t)m * N + n]) = v0;
            *reinterpret_cast<float2*>(&C[(size_t)(m + 8) * N + n]) = v1;
        }
    }
}

// ---------------------------------------------------------------------------
// Attention (unchanged from round 4): block per query, warp = head.
// ---------------------------------------------------------------------------
__device__ __forceinline__ float warpSum(float v) {
#pragma unroll
    for (int o = 16; o > 0; o >>= 1) v += __shfl_xor_sync(0xffffffffu, v, o);
    return v;
}
__device__ __forceinline__ float warpMax(float v) {
#pragma unroll
    for (int o = 16; o > 0; o >>= 1) v = fmaxf(v, __shfl_xor_sync(0xffffffffu, v, o));
    return v;
}

__device__ __forceinline__ void pack_hilo(float4 v, uint2& hi, uint2& lo) {
    unsigned short h[4], l[4];
    float vv[4] = {v.x, v.y, v.z, v.w};
#pragma unroll
    for (int j = 0; j < 4; j++) {
        __nv_bfloat16 hb = __float2bfloat16_rn(vv[j]);
        h[j] = __bfloat16_as_ushort(hb);
        l[j] = __bfloat16_as_ushort(__float2bfloat16_rn(vv[j] - __bfloat162float(hb)));
    }
    hi = make_uint2((uint32_t)h[0] | ((uint32_t)h[1] << 16),
                    (uint32_t)h[2] | ((uint32_t)h[3] << 16));
    lo = make_uint2((uint32_t)l[0] | ((uint32_t)l[1] << 16),
                    (uint32_t)l[2] | ((uint32_t)l[3] << 16));
}

__global__ void __launch_bounds__(256)
attn_kernel(const float* __restrict__ qkv,
            __nv_bfloat16* __restrict__ ahi, __nv_bfloat16* __restrict__ alo) {
    __shared__ float sims[HEADS][128];
    __shared__ int   rows[HEADS][128];

    const int bid = blockIdx.x;
    const int tid = threadIdx.x;

    if (bid == 2047) {
        for (int c = tid; c < INNER; c += 256) {
            float v = qkv[2 * INNER + c];
            __nv_bfloat16 hb = __float2bfloat16_rn(v);
            ahi[c] = hb;
            alo[c] = __float2bfloat16_rn(v - __bfloat162float(hb));
        }
        return;
    }

    const int qi   = bid;
    const int h    = tid >> 5;
    const int lane = tid & 31;
    const int g    = lane >> 3;
    const int li   = lane & 7;

    const float* qrow = qkv + (size_t)(qi + 1) * QKVW + h * DHEAD;
    float4 q4a = *reinterpret_cast<const float4*>(qrow + li * 4);
    float4 q4b = *reinterpret_cast<const float4*>(qrow + 32 + li * 4);
    const float sc = 0.125f;
    q4a.x *= sc; q4a.y *= sc; q4a.z *= sc; q4a.w *= sc;
    q4b.x *= sc; q4b.y *= sc; q4b.z *= sc; q4b.w *= sc;

    const int f  = qi >> 10;
    const int yy = (qi >> 5) & 31;
    const int xx = qi & 31;

    const float* kbase = qkv + INNER;
    const float* vbase = qkv + 2 * INNER;

#pragma unroll 4
    for (int it = 0; it < 32; it++) {
        const int s = it * 4 + g;
        int row = 0;
        bool valid;
        if (s == 0) {
            valid = true;
        } else {
            const int jj = s - 1;
            const int df = jj / 25;
            const int rem = jj - df * 25;
            const int dh = rem / 5;
            const int dw = rem - dh * 5;
            const int nf = f + df - 2, nh = yy + dh - 2, nw = xx + dw - 2;
            valid = (jj < 125) & ((unsigned)nf < 2u) & ((unsigned)nh < 32u) &
                    ((unsigned)nw < 32u);
            const int nidx = (nf << 10) + (nh << 5) + nw;
            valid = valid && (nidx <= qi);
            row = nidx + 1;
        }
        float part = 0.0f;
        if (valid) {
            const float* kr = kbase + (size_t)row * QKVW + h * DHEAD;
            float4 k4a = *reinterpret_cast<const float4*>(kr + li * 4);
            float4 k4b = *reinterpret_cast<const float4*>(kr + 32 + li * 4);
            part = q4a.x * k4a.x + q4a.y * k4a.y + q4a.z * k4a.z + q4a.w * k4a.w +
                   q4b.x * k4b.x + q4b.y * k4b.y + q4b.z * k4b.z + q4b.w * k4b.w;
        }
        part += __shfl_xor_sync(0xffffffffu, part, 1);
        part += __shfl_xor_sync(0xffffffffu, part, 2);
        part += __shfl_xor_sync(0xffffffffu, part, 4);
        if (li == 0) {
            sims[h][s] = valid ? part : -FLT_MAX;
            rows[h][s] = row;
        }
    }
    __syncwarp();

    float sv[4];
#pragma unroll
    for (int t = 0; t < 4; t++) {
        const int s = lane + 32 * t;
        sv[t] = (s < 126) ? sims[h][s] : -FLT_MAX;
    }
    float m = fmaxf(fmaxf(sv[0], sv[1]), fmaxf(sv[2], sv[3]));
    m = warpMax(m);
    float z = 0.0f;
#pragma unroll
    for (int t = 0; t < 4; t++) {
        sv[t] = __expf(sv[t] - m);
        z += sv[t];
    }
    z = warpSum(z);
    const float invz = 1.0f / z;
#pragma unroll
    for (int t = 0; t < 4; t++) {
        const int s = lane + 32 * t;
        if (s < 126) sims[h][s] = sv[t] * invz;
    }
    __syncwarp();

    float4 aa = make_float4(0.f, 0.f, 0.f, 0.f);
    float4 ab = make_float4(0.f, 0.f, 0.f, 0.f);
#pragma unroll 4
    for (int it = 0; it < 32; it++) {
        const int s = it * 4 + g;
        if (s < 126) {
            const float p = sims[h][s];
            if (p != 0.0f) {
                const int row = rows[h][s];
                const float* vr = vbase + (size_t)row * QKVW + h * DHEAD;
                float4 v4a = *reinterpret_cast<const float4*>(vr + li * 4);
                float4 v4b = *reinterpret_cast<const float4*>(vr + 32 + li * 4);
                aa.x = fmaf(p, v4a.x, aa.x); aa.y = fmaf(p, v4a.y, aa.y);
                aa.z = fmaf(p, v4a.z, aa.z); aa.w = fmaf(p, v4a.w, aa.w);
                ab.x = fmaf(p, v4b.x, ab.x); ab.y = fmaf(p, v4b.y, ab.y);
                ab.z = fmaf(p, v4b.z, ab.z); ab.w = fmaf(p, v4b.w, ab.w);
            }
        }
    }

#pragma unroll
    for (int off = 8; off <= 16; off <<= 1) {
        aa.x += __shfl_xor_sync(0xffffffffu, aa.x, off);
        aa.y += __shfl_xor_sync(0xffffffffu, aa.y, off);
        aa.z += __shfl_xor_sync(0xffffffffu, aa.z, off);
        aa.w += __shfl_xor_sync(0xffffffffu, aa.w, off);
        ab.x += __shfl_xor_sync(0xffffffffu, ab.x, off);
        ab.y += __shfl_xor_sync(0xffffffffu, ab.y, off);
        ab.z += __shfl_xor_sync(0xffffffffu, ab.z, off);
        ab.w += __shfl_xor_sync(0xffffffffu, ab.w, off);
    }

    if (g == 0) {
        const size_t obase = (size_t)(qi + 1) * INNER + h * DHEAD;
        uint2 hi, lo;
        pack_hilo(aa, hi, lo);
        *reinterpret_cast<uint2*>(ahi + obase + li * 4) = hi;
        *reinterpret_cast<uint2*>(alo + obase + li * 4) = lo;
        pack_hilo(ab, hi, lo);
        *reinterpret_cast<uint2*>(ahi + obase + 32 + li * 4) = hi;
        *reinterpret_cast<uint2*>(alo + obase + 32 + li * 4) = lo;
    }
}

// ---------------------------------------------------------------------------
extern "C" void kernel_launch(void* const* d_in, const int* in_sizes, int n_in,
                              void* d_out, int out_size) {
    const float* x     = (const float*)d_in[0];  // (1, 2048, 512)
    const float* w_qkv = (const float*)d_in[1];  // (512, 1536)
    const float* w_out = (const float*)d_in[2];  // (512, 512)
    const float* b_out = (const float*)d_in[3];  // (512,)
    float* out = (float*)d_out;

    float* qkv;
    __nv_bfloat16 *xhi, *xlo, *w1hiT, *w1loT, *ahi, *alo, *w2hiT, *w2loT;
    cudaGetSymbolAddress((void**)&qkv,   g_qkv);
    cudaGetSymbolAddress((void**)&xhi,   g_xhi);
    cudaGetSymbolAddress((void**)&xlo,   g_xlo);
    cudaGetSymbolAddress((void**)&w1hiT, g_w1hiT);
    cudaGetSymbolAddress((void**)&w1loT, g_w1loT);
    cudaGetSymbolAddress((void**)&ahi,   g_ahi);
    cudaGetSymbolAddress((void**)&alo,   g_alo);
    cudaGetSymbolAddress((void**)&w2hiT, g_w2hiT);
    cudaGetSymbolAddress((void**)&w2loT, g_w2loT);

    const int smem1 = 4 * (5120 + 10240);   // 61440 for BN=128
    const int smem2 = 4 * (5120 + 5120);    // 40960 for BN=64
    cudaFuncSetAttribute(gemm_ca_kernel<128>,
                         cudaFuncAttributeMaxDynamicSharedMemorySize, smem1);
    cudaFuncSetAttribute(gemm_ca_kernel<64>,
                         cudaFuncAttributeMaxDynamicSharedMemorySize, smem2);

    // split x (layout preserved); transpose-split weights to [N, K]
    split_bf16_kernel<<<(NTOK * INNER / 4 + 255) / 256, 256>>>(x, xhi, xlo,
                                                               NTOK * INNER);
    tsplit_kernel<<<dim3(QKVW / 32, KDIM / 32), 256>>>(w_qkv, w1hiT, w1loT,
                                                       KDIM, QKVW);
    tsplit_kernel<<<dim3(INNER / 32, KDIM / 32), 256>>>(w_out, w2hiT, w2loT,
                                                        KDIM, INNER);

    // 1) qkv = x @ w_qkv   (bf16x3, cp.async pipeline)
    gemm_ca_kernel<128><<<dim3(QKVW / 128, NTOK / 64), 256, smem1>>>(
        xhi, xlo, w1hiT, w1loT, qkv, nullptr, QKVW);

    // 2) windowed causal attention (writes bf16 hi/lo directly)
    attn_kernel<<<2048, 256>>>(qkv, ahi, alo);

    // 3) out = attn @ w_out + b_out
    gemm_ca_kernel<64><<<dim3(INNER / 64, NTOK / 64), 256, smem2>>>(
        ahi, alo, w2hiT, w2loT, out, b_out, INNER);
}

// round 7
// speedup vs baseline: 2.0013x; 1.1127x over previous
#include <cuda_runtime.h>
#include <cuda_bf16.h>
#include <cstdint>
#include <float.h>
#include <math.h>

// Problem constants
#define NTOK   2048          // N = F*H*W = 2*32*32
#define INNER  512
#define QKVW   1536          // 3*INNER
#define HEADS  8
#define DHEAD  64
#define KDIM   512           // GEMM K for both GEMMs

// Scratch (device globals; no allocation allowed)
__device__ float g_qkv[NTOK * QKVW];
__device__ __nv_bfloat16 g_xhi[NTOK * INNER],    g_xlo[NTOK * INNER];
__device__ __nv_bfloat16 g_w1hiT[QKVW * INNER],  g_w1loT[QKVW * INNER];   // [N,K]
__device__ __nv_bfloat16 g_ahi[NTOK * INNER],    g_alo[NTOK * INNER];
__device__ __nv_bfloat16 g_w2hiT[INNER * INNER], g_w2loT[INNER * INNER];  // [N,K]

// ---------------------------------------------------------------------------
// Split fp32 -> (hi, lo) bf16, same layout
// ---------------------------------------------------------------------------
__global__ void __launch_bounds__(256)
split_bf16_kernel(const float* __restrict__ in,
                  __nv_bfloat16* __restrict__ hi,
                  __nv_bfloat16* __restrict__ lo, int n) {
    int base = (blockIdx.x * 256 + threadIdx.x) * 4;
    if (base < n) {
        float4 v = *reinterpret_cast<const float4*>(in + base);
        float vv[4] = {v.x, v.y, v.z, v.w};
        unsigned short h[4], l[4];
#pragma unroll
        for (int j = 0; j < 4; j++) {
            __nv_bfloat16 hb = __float2bfloat16_rn(vv[j]);
            h[j] = __bfloat16_as_ushort(hb);
            l[j] = __bfloat16_as_ushort(__float2bfloat16_rn(vv[j] - __bfloat162float(hb)));
        }
        uint2 ho = make_uint2((uint32_t)h[0] | ((uint32_t)h[1] << 16),
                              (uint32_t)h[2] | ((uint32_t)h[3] << 16));
        uint2 lz = make_uint2((uint32_t)l[0] | ((uint32_t)l[1] << 16),
                              (uint32_t)l[2] | ((uint32_t)l[3] << 16));
        *reinterpret_cast<uint2*>(hi + base) = ho;
        *reinterpret_cast<uint2*>(lo + base) = lz;
    }
}

// ---------------------------------------------------------------------------
// Transpose + split: in [K, N] fp32 -> hiT/loT [N, K] bf16
// ---------------------------------------------------------------------------
__global__ void __launch_bounds__(256)
tsplit_kernel(const float* __restrict__ in, __nv_bfloat16* __restrict__ hiT,
              __nv_bfloat16* __restrict__ loT, int K, int N) {
    __shared__ float sm[32][33];
    const int n0 = blockIdx.x * 32, k0 = blockIdx.y * 32;
    const int tx = threadIdx.x & 31, ty = threadIdx.x >> 5;
#pragma unroll
    for (int i = 0; i < 4; i++)
        sm[ty + i * 8][tx] = in[(size_t)(k0 + ty + i * 8) * N + n0 + tx];
    __syncthreads();
#pragma unroll
    for (int i = 0; i < 4; i++) {
        int nr = ty + i * 8;
        float v = sm[tx][nr];
        __nv_bfloat16 hb = __float2bfloat16_rn(v);
        hiT[(size_t)(n0 + nr) * K + k0 + tx] = hb;
        loT[(size_t)(n0 + nr) * K + k0 + tx] =
            __float2bfloat16_rn(v - __bfloat162float(hb));
    }
}

// ---------------------------------------------------------------------------
// bf16x3 mma.sync GEMM with cp.async 4-stage pipeline + ldmatrix fragments.
//   C[M,N] = Ahi*Bhi + Alo*Bhi + Ahi*Blo (+bias)
// A: [M, K=512] bf16 (hi/lo), B: [N, K=512] bf16 (hi/lo)  — both K-major.
// CTA tile 64 x BN, BK=32, 8 warps (2x4), warp tile 32 x (BN/4).
// smem rows padded to 20 u32 (80B): conflict-free for cp.async AND ldmatrix.
// ---------------------------------------------------------------------------
__device__ __forceinline__ void mma_bf16(float* c, const uint32_t* a, const uint32_t* b) {
    asm volatile(
        "mma.sync.aligned.m16n8k16.row.col.f32.bf16.bf16.f32 "
        "{%0,%1,%2,%3}, {%4,%5,%6,%7}, {%8,%9}, {%0,%1,%2,%3};\n"
        : "+f"(c[0]), "+f"(c[1]), "+f"(c[2]), "+f"(c[3])
        : "r"(a[0]), "r"(a[1]), "r"(a[2]), "r"(a[3]), "r"(b[0]), "r"(b[1]));
}

__device__ __forceinline__ void ldsm_x4(uint32_t addr, uint32_t* r) {
    asm volatile("ldmatrix.sync.aligned.m8n8.x4.shared.b16 {%0,%1,%2,%3}, [%4];"
                 : "=r"(r[0]), "=r"(r[1]), "=r"(r[2]), "=r"(r[3]) : "r"(addr));
}

__device__ __forceinline__ uint32_t smem_u32(const void* p) {
    uint32_t a;
    asm("{ .reg .u64 t; cvta.to.shared.u64 t, %1; cvt.u32.u64 %0, t; }"
        : "=r"(a) : "l"(p));
    return a;
}

template <int BN>
__global__ void __launch_bounds__(256, 3)
gemm_ca_kernel(const __nv_bfloat16* __restrict__ Ahi,
               const __nv_bfloat16* __restrict__ Alo,
               const __nv_bfloat16* __restrict__ Bhi,
               const __nv_bfloat16* __restrict__ Blo,
               float* __restrict__ C, const float* __restrict__ bias, int N) {
    constexpr int BM = 64, K = KDIM;
    constexpr int SA = 20;                       // u32 per smem row (32 bf16 + pad)
    constexpr int ABYTES = BM * SA * 4;          // 5120
    constexpr int BBYTES = BN * SA * 4;          // 10240 (BN=128) / 5120
    constexpr int STAGE  = ABYTES + BBYTES;
    constexpr int NCH    = 48;                   // 3 segments * 512/32
    constexpr int WN = BN / 4;
    constexpr int MT = 2, NT = WN / 8;
    constexpr int NP = NT / 2;                   // B ldmatrix.x4 count per ks
    constexpr int BCH = BN * 4 / 256;            // B 16B-chunks per thread

    extern __shared__ char dsm[];

    const int tid  = threadIdx.x;
    const int lane = tid & 31, wid = tid >> 5;
    const int gid  = lane >> 2, tig = lane & 3;
    const int wm   = wid >> 2,  wn  = wid & 3;
    const int bm   = blockIdx.y * BM, bn = blockIdx.x * BN;
    const uint32_t sbase = smem_u32(dsm);

    // ldmatrix lane addressing: row = lane&15, k-halve offset = (lane>>4)*16B
    const int lrow = lane & 15;
    const int lkof = (lane >> 4) * 16;

    float acc[MT][NT][4];
#pragma unroll
    for (int i = 0; i < MT; i++)
#pragma unroll
        for (int j = 0; j < NT; j++)
#pragma unroll
            for (int q = 0; q < 4; q++) acc[i][j][q] = 0.0f;

#define PREFETCH(c)                                                            \
    {                                                                          \
        const int _s = (c) & 3;                                                \
        const int _seg = (c) >> 4;                                             \
        const int _kk = ((c) & 15) * 32;                                       \
        const __nv_bfloat16* _Ap = (_seg == 1) ? Alo : Ahi;                    \
        const __nv_bfloat16* _Bp = (_seg == 2) ? Blo : Bhi;                    \
        const uint32_t _ab = sbase + _s * STAGE;                               \
        const uint32_t _bb = _ab + ABYTES;                                     \
        {                                                                      \
            const int _r = tid >> 2, _ch = tid & 3;                            \
            asm volatile("cp.async.ca.shared.global [%0], [%1], 16;"           \
                :: "r"(_ab + _r * 80 + _ch * 16),                              \
                   "l"(_Ap + (size_t)(bm + _r) * K + _kk + _ch * 8));          \
        }                                                                      \
        _Pragma("unroll")                                                      \
        for (int _i = 0; _i < BCH; _i++) {                                     \
            const int _u = tid + _i * 256;                                     \
            const int _r = _u >> 2, _ch = _u & 3;                              \
            asm volatile("cp.async.ca.shared.global [%0], [%1], 16;"           \
                :: "r"(_bb + _r * 80 + _ch * 16),                              \
                   "l"(_Bp + (size_t)(bn + _r) * K + _kk + _ch * 8));          \
        }                                                                      \
    }

    PREFETCH(0); asm volatile("cp.async.commit_group;" ::: "memory");
    PREFETCH(1); asm volatile("cp.async.commit_group;" ::: "memory");
    PREFETCH(2); asm volatile("cp.async.commit_group;" ::: "memory");

    for (int c = 0; c < NCH; c++) {
        asm volatile("cp.async.wait_group 2;" ::: "memory");
        __syncthreads();

        // prefetch next stage first (writes stage (c+3)&3 = (c-1)&3, whose
        // reads all finished before the barrier above)
        if (c + 3 < NCH) PREFETCH(c + 3);
        asm volatile("cp.async.commit_group;" ::: "memory");

        const uint32_t sa = sbase + (c & 3) * STAGE;
        const uint32_t aB = sa + (uint32_t)(wm * 32 + lrow) * 80 + lkof;
        const uint32_t bB = sa + ABYTES + (uint32_t)(wn * WN + lrow) * 80 + lkof;

#pragma unroll
        for (int ks = 0; ks < 2; ks++) {
            uint32_t a[MT][4], b[NT][2];
#pragma unroll
            for (int mt = 0; mt < MT; mt++)
                ldsm_x4(aB + mt * 16 * 80 + ks * 32, a[mt]);
#pragma unroll
            for (int p = 0; p < NP; p++) {
                uint32_t r[4];
                ldsm_x4(bB + p * 16 * 80 + ks * 32, r);
                b[2 * p + 0][0] = r[0];
                b[2 * p + 1][0] = r[1];
                b[2 * p + 0][1] = r[2];
                b[2 * p + 1][1] = r[3];
            }
#pragma unroll
            for (int mt = 0; mt < MT; mt++)
#pragma unroll
                for (int nt = 0; nt < NT; nt++)
                    mma_bf16(acc[mt][nt], a[mt], b[nt]);
        }
    }
#undef PREFETCH

#pragma unroll
    for (int mt = 0; mt < MT; mt++) {
#pragma unroll
        for (int nt = 0; nt < NT; nt++) {
            const int m = bm + wm * 32 + mt * 16 + gid;
            const int n = bn + wn * WN + nt * 8 + 2 * tig;
            float b0 = bias ? bias[n] : 0.0f;
            float b1 = bias ? bias[n + 1] : 0.0f;
            float2 v0 = make_float2(acc[mt][nt][0] + b0, acc[mt][nt][1] + b1);
            float2 v1 = make_float2(acc[mt][nt][2] + b0, acc[mt][nt][3] + b1);
            *reinterpret_cast<float2*>(&C[(size_t)m * N + n]) = v0;
            *reinterpret_cast<float2*>(&C[(size_t)(m + 8) * N + n]) = v1;
        }
    }
}

// ---------------------------------------------------------------------------
// Attention (unchanged): block per query, warp = head.
// ---------------------------------------------------------------------------
__device__ __forceinline__ float warpSum(float v) {
#pragma unroll
    for (int o = 16; o > 0; o >>= 1) v += __shfl_xor_sync(0xffffffffu, v, o);
    return v;
}
__device__ __forceinline__ float warpMax(float v) {
#pragma unroll
    for (int o = 16; o > 0; o >>= 1) v = fmaxf(v, __shfl_xor_sync(0xffffffffu, v, o));
    return v;
}

__device__ __forceinline__ void pack_hilo(float4 v, uint2& hi, uint2& lo) {
    unsigned short h[4], l[4];
    float vv[4] = {v.x, v.y, v.z, v.w};
#pragma unroll
    for (int j = 0; j < 4; j++) {
        __nv_bfloat16 hb = __float2bfloat16_rn(vv[j]);
        h[j] = __bfloat16_as_ushort(hb);
        l[j] = __bfloat16_as_ushort(__float2bfloat16_rn(vv[j] - __bfloat162float(hb)));
    }
    hi = make_uint2((uint32_t)h[0] | ((uint32_t)h[1] << 16),
                    (uint32_t)h[2] | ((uint32_t)h[3] << 16));
    lo = make_uint2((uint32_t)l[0] | ((uint32_t)l[1] << 16),
                    (uint32_t)l[2] | ((uint32_t)l[3] << 16));
}

__global__ void __launch_bounds__(256)
attn_kernel(const float* __restrict__ qkv,
            __nv_bfloat16* __restrict__ ahi, __nv_bfloat16* __restrict__ alo) {
    __shared__ float sims[HEADS][128];
    __shared__ int   rows[HEADS][128];

    const int bid = blockIdx.x;
    const int tid = threadIdx.x;

    if (bid == 2047) {
        for (int c = tid; c < INNER; c += 256) {
            float v = qkv[2 * INNER + c];
            __nv_bfloat16 hb = __float2bfloat16_rn(v);
            ahi[c] = hb;
            alo[c] = __float2bfloat16_rn(v - __bfloat162float(hb));
        }
        return;
    }

    const int qi   = bid;
    const int h    = tid >> 5;
    const int lane = tid & 31;
    const int g    = lane >> 3;
    const int li   = lane & 7;

    const float* qrow = qkv + (size_t)(qi + 1) * QKVW + h * DHEAD;
    float4 q4a = *reinterpret_cast<const float4*>(qrow + li * 4);
    float4 q4b = *reinterpret_cast<const float4*>(qrow + 32 + li * 4);
    const float sc = 0.125f;
    q4a.x *= sc; q4a.y *= sc; q4a.z *= sc; q4a.w *= sc;
    q4b.x *= sc; q4b.y *= sc; q4b.z *= sc; q4b.w *= sc;

    const int f  = qi >> 10;
    const int yy = (qi >> 5) & 31;
    const int xx = qi & 31;

    const float* kbase = qkv + INNER;
    const float* vbase = qkv + 2 * INNER;

#pragma unroll 4
    for (int it = 0; it < 32; it++) {
        const int s = it * 4 + g;
        int row = 0;
        bool valid;
        if (s == 0) {
            valid = true;
        } else {
            const int jj = s - 1;
            const int df = jj / 25;
            const int rem = jj - df * 25;
            const int dh = rem / 5;
            const int dw = rem - dh * 5;
            const int nf = f + df - 2, nh = yy + dh - 2, nw = xx + dw - 2;
            valid = (jj < 125) & ((unsigned)nf < 2u) & ((unsigned)nh < 32u) &
                    ((unsigned)nw < 32u);
            const int nidx = (nf << 10) + (nh << 5) + nw;
            valid = valid && (nidx <= qi);
            row = nidx + 1;
        }
        float part = 0.0f;
        if (valid) {
            const float* kr = kbase + (size_t)row * QKVW + h * DHEAD;
            float4 k4a = *reinterpret_cast<const float4*>(kr + li * 4);
            float4 k4b = *reinterpret_cast<const float4*>(kr + 32 + li * 4);
            part = q4a.x * k4a.x + q4a.y * k4a.y + q4a.z * k4a.z + q4a.w * k4a.w +
                   q4b.x * k4b.x + q4b.y * k4b.y + q4b.z * k4b.z + q4b.w * k4b.w;
        }
        part += __shfl_xor_sync(0xffffffffu, part, 1);
        part += __shfl_xor_sync(0xffffffffu, part, 2);
        part += __shfl_xor_sync(0xffffffffu, part, 4);
        if (li == 0) {
            sims[h][s] = valid ? part : -FLT_MAX;
            rows[h][s] = row;
        }
    }
    __syncwarp();

    float sv[4];
#pragma unroll
    for (int t = 0; t < 4; t++) {
        const int s = lane + 32 * t;
        sv[t] = (s < 126) ? sims[h][s] : -FLT_MAX;
    }
    float m = fmaxf(fmaxf(sv[0], sv[1]), fmaxf(sv[2], sv[3]));
    m = warpMax(m);
    float z = 0.0f;
#pragma unroll
    for (int t = 0; t < 4; t++) {
        sv[t] = __expf(sv[t] - m);
        z += sv[t];
    }
    z = warpSum(z);
    const float invz = 1.0f / z;
#pragma unroll
    for (int t = 0; t < 4; t++) {
        const int s = lane + 32 * t;
        if (s < 126) sims[h][s] = sv[t] * invz;
    }
    __syncwarp();

    float4 aa = make_float4(0.f, 0.f, 0.f, 0.f);
    float4 ab = make_float4(0.f, 0.f, 0.f, 0.f);
#pragma unroll 4
    for (int it = 0; it < 32; it++) {
        const int s = it * 4 + g;
        if (s < 126) {
            const float p = sims[h][s];
            if (p != 0.0f) {
                const int row = rows[h][s];
                const float* vr = vbase + (size_t)row * QKVW + h * DHEAD;
                float4 v4a = *reinterpret_cast<const float4*>(vr + li * 4);
                float4 v4b = *reinterpret_cast<const float4*>(vr + 32 + li * 4);
                aa.x = fmaf(p, v4a.x, aa.x); aa.y = fmaf(p, v4a.y, aa.y);
                aa.z = fmaf(p, v4a.z, aa.z); aa.w = fmaf(p, v4a.w, aa.w);
                ab.x = fmaf(p, v4b.x, ab.x); ab.y = fmaf(p, v4b.y, ab.y);
                ab.z = fmaf(p, v4b.z, ab.z); ab.w = fmaf(p, v4b.w, ab.w);
            }
        }
    }

#pragma unroll
    for (int off = 8; off <= 16; off <<= 1) {
        aa.x += __shfl_xor_sync(0xffffffffu, aa.x, off);
        aa.y += __shfl_xor_sync(0xffffffffu, aa.y, off);
        aa.z += __shfl_xor_sync(0xffffffffu, aa.z, off);
        aa.w += __shfl_xor_sync(0xffffffffu, aa.w, off);
        ab.x += __shfl_xor_sync(0xffffffffu, ab.x, off);
        ab.y += __shfl_xor_sync(0xffffffffu, ab.y, off);
        ab.z += __shfl_xor_sync(0xffffffffu, ab.z, off);
        ab.w += __shfl_xor_sync(0xffffffffu, ab.w, off);
    }

    if (g == 0) {
        const size_t obase = (size_t)(qi + 1) * INNER + h * DHEAD;
        uint2 hi, lo;
        pack_hilo(aa, hi, lo);
        *reinterpret_cast<uint2*>(ahi + obase + li * 4) = hi;
        *reinterpret_cast<uint2*>(alo + obase + li * 4) = lo;
        pack_hilo(ab, hi, lo);
        *reinterpret_cast<uint2*>(ahi + obase + 32 + li * 4) = hi;
        *reinterpret_cast<uint2*>(alo + obase + 32 + li * 4) = lo;
    }
}

// ---------------------------------------------------------------------------
extern "C" void kernel_launch(void* const* d_in, const int* in_sizes, int n_in,
                              void* d_out, int out_size) {
    const float* x     = (const float*)d_in[0];  // (1, 2048, 512)
    const float* w_qkv = (const float*)d_in[1];  // (512, 1536)
    const float* w_out = (const float*)d_in[2];  // (512, 512)
    const float* b_out = (const float*)d_in[3];  // (512,)
    float* out = (float*)d_out;

    float* qkv;
    __nv_bfloat16 *xhi, *xlo, *w1hiT, *w1loT, *ahi, *alo, *w2hiT, *w2loT;
    cudaGetSymbolAddress((void**)&qkv,   g_qkv);
    cudaGetSymbolAddress((void**)&xhi,   g_xhi);
    cudaGetSymbolAddress((void**)&xlo,   g_xlo);
    cudaGetSymbolAddress((void**)&w1hiT, g_w1hiT);
    cudaGetSymbolAddress((void**)&w1loT, g_w1loT);
    cudaGetSymbolAddress((void**)&ahi,   g_ahi);
    cudaGetSymbolAddress((void**)&alo,   g_alo);
    cudaGetSymbolAddress((void**)&w2hiT, g_w2hiT);
    cudaGetSymbolAddress((void**)&w2loT, g_w2loT);

    const int smem1 = 4 * (5120 + 10240);   // 61440 for BN=128
    const int smem2 = 4 * (5120 + 5120);    // 40960 for BN=64
    cudaFuncSetAttribute(gemm_ca_kernel<128>,
                         cudaFuncAttributeMaxDynamicSharedMemorySize, smem1);
    cudaFuncSetAttribute(gemm_ca_kernel<64>,
                         cudaFuncAttributeMaxDynamicSharedMemorySize, smem2);

    // split x (layout preserved); transpose-split weights to [N, K]
    split_bf16_kernel<<<(NTOK * INNER / 4 + 255) / 256, 256>>>(x, xhi, xlo,
                                                               NTOK * INNER);
    tsplit_kernel<<<dim3(QKVW / 32, KDIM / 32), 256>>>(w_qkv, w1hiT, w1loT,
                                                       KDIM, QKVW);
    tsplit_kernel<<<dim3(INNER / 32, KDIM / 32), 256>>>(w_out, w2hiT, w2loT,
                                                        KDIM, INNER);

    // 1) qkv = x @ w_qkv   (bf16x3, cp.async + ldmatrix pipeline)
    gemm_ca_kernel<128><<<dim3(QKVW / 128, NTOK / 64), 256, smem1>>>(
        xhi, xlo, w1hiT, w1loT, qkv, nullptr, QKVW);

    // 2) windowed causal attention (writes bf16 hi/lo directly)
    attn_kernel<<<2048, 256>>>(qkv, ahi, alo);

    // 3) out = attn @ w_out + b_out
    gemm_ca_kernel<64><<<dim3(INNER / 64, NTOK / 64), 256, smem2>>>(
        ahi, alo, w2hiT, w2loT, out, b_out, INNER);
}

// round 8
// speedup vs baseline: 2.2457x; 1.1221x over previous
#include <cuda_runtime.h>
#include <cuda_bf16.h>
#include <cstdint>
#include <float.h>
#include <math.h>

// Problem constants
#define NTOK   2048          // N = F*H*W = 2*32*32
#define INNER  512
#define QKVW   1536          // 3*INNER
#define HEADS  8
#define DHEAD  64
#define KDIM   512           // GEMM K for both GEMMs

// Scratch (device globals; no allocation allowed)
__device__ float g_qkv[NTOK * QKVW];
__device__ __nv_bfloat16 g_xhi[NTOK * INNER],    g_xlo[NTOK * INNER];
__device__ __nv_bfloat16 g_w1hiT[QKVW * INNER],  g_w1loT[QKVW * INNER];   // [N,K]
__device__ __nv_bfloat16 g_ahi[NTOK * INNER],    g_alo[NTOK * INNER];
__device__ __nv_bfloat16 g_w2hiT[INNER * INNER], g_w2loT[INNER * INNER];  // [N,K]

// ---------------------------------------------------------------------------
// Split fp32 -> (hi, lo) bf16, same layout
// ---------------------------------------------------------------------------
__global__ void __launch_bounds__(256)
split_bf16_kernel(const float* __restrict__ in,
                  __nv_bfloat16* __restrict__ hi,
                  __nv_bfloat16* __restrict__ lo, int n) {
    int base = (blockIdx.x * 256 + threadIdx.x) * 4;
    if (base < n) {
        float4 v = *reinterpret_cast<const float4*>(in + base);
        float vv[4] = {v.x, v.y, v.z, v.w};
        unsigned short h[4], l[4];
#pragma unroll
        for (int j = 0; j < 4; j++) {
            __nv_bfloat16 hb = __float2bfloat16_rn(vv[j]);
            h[j] = __bfloat16_as_ushort(hb);
            l[j] = __bfloat16_as_ushort(__float2bfloat16_rn(vv[j] - __bfloat162float(hb)));
        }
        uint2 ho = make_uint2((uint32_t)h[0] | ((uint32_t)h[1] << 16),
                              (uint32_t)h[2] | ((uint32_t)h[3] << 16));
        uint2 lz = make_uint2((uint32_t)l[0] | ((uint32_t)l[1] << 16),
                              (uint32_t)l[2] | ((uint32_t)l[3] << 16));
        *reinterpret_cast<uint2*>(hi + base) = ho;
        *reinterpret_cast<uint2*>(lo + base) = lz;
    }
}

// ---------------------------------------------------------------------------
// Transpose + split: in [K, N] fp32 -> hiT/loT [N, K] bf16
// ---------------------------------------------------------------------------
__global__ void __launch_bounds__(256)
tsplit_kernel(const float* __restrict__ in, __nv_bfloat16* __restrict__ hiT,
              __nv_bfloat16* __restrict__ loT, int K, int N) {
    __shared__ float sm[32][33];
    const int n0 = blockIdx.x * 32, k0 = blockIdx.y * 32;
    const int tx = threadIdx.x & 31, ty = threadIdx.x >> 5;
#pragma unroll
    for (int i = 0; i < 4; i++)
        sm[ty + i * 8][tx] = in[(size_t)(k0 + ty + i * 8) * N + n0 + tx];
    __syncthreads();
#pragma unroll
    for (int i = 0; i < 4; i++) {
        int nr = ty + i * 8;
        float v = sm[tx][nr];
        __nv_bfloat16 hb = __float2bfloat16_rn(v);
        hiT[(size_t)(n0 + nr) * K + k0 + tx] = hb;
        loT[(size_t)(n0 + nr) * K + k0 + tx] =
            __float2bfloat16_rn(v - __bfloat162float(hb));
    }
}

// ---------------------------------------------------------------------------
// bf16x3 shared-operand GEMM:
//   per k-chunk load Ahi/Alo/Bhi/Blo ONCE, run 3 MMA combos into one acc:
//   C = Ahi*Bhi + Alo*Bhi + Ahi*Blo (+bias)
// A: [M, K=512] bf16 (hi/lo), B: [N, K=512] bf16 (hi/lo) — both K-major.
// CTA tile 64 x BN, BK=32, 8 warps (2x4), warp tile 32 x (BN/4).
// smem rows padded to 80B: conflict-free for cp.async and ldmatrix.
// ---------------------------------------------------------------------------
__device__ __forceinline__ void mma_bf16(float* c, const uint32_t* a, const uint32_t* b) {
    asm volatile(
        "mma.sync.aligned.m16n8k16.row.col.f32.bf16.bf16.f32 "
        "{%0,%1,%2,%3}, {%4,%5,%6,%7}, {%8,%9}, {%0,%1,%2,%3};\n"
        : "+f"(c[0]), "+f"(c[1]), "+f"(c[2]), "+f"(c[3])
        : "r"(a[0]), "r"(a[1]), "r"(a[2]), "r"(a[3]), "r"(b[0]), "r"(b[1]));
}

__device__ __forceinline__ void ldsm_x4(uint32_t addr, uint32_t* r) {
    asm volatile("ldmatrix.sync.aligned.m8n8.x4.shared.b16 {%0,%1,%2,%3}, [%4];"
                 : "=r"(r[0]), "=r"(r[1]), "=r"(r[2]), "=r"(r[3]) : "r"(addr));
}

__device__ __forceinline__ uint32_t smem_u32(const void* p) {
    uint32_t a;
    asm("{ .reg .u64 t; cvta.to.shared.u64 t, %1; cvt.u32.u64 %0, t; }"
        : "=r"(a) : "l"(p));
    return a;
}

template <int BN, int S>
__global__ void __launch_bounds__(256, 2)
gemm_so_kernel(const __nv_bfloat16* __restrict__ Ahi,
               const __nv_bfloat16* __restrict__ Alo,
               const __nv_bfloat16* __restrict__ Bhi,
               const __nv_bfloat16* __restrict__ Blo,
               float* __restrict__ C, const float* __restrict__ bias, int N) {
    constexpr int BM = 64, K = KDIM;
    constexpr int AT = BM * 80;                  // one A tile bytes (5120)
    constexpr int BT = BN * 80;                  // one B tile bytes
    constexpr int STAGE = 2 * AT + 2 * BT;       // Ahi|Alo|Bhi|Blo
    constexpr int NCH = K / 32;                  // 16
    constexpr int WN = BN / 4;
    constexpr int MT = 2, NT = WN / 8, NP = NT / 2;
    constexpr int BCH = BN * 4 / 256;            // B 16B-chunks per thread

    extern __shared__ char dsm[];

    const int tid  = threadIdx.x;
    const int lane = tid & 31, wid = tid >> 5;
    const int gid  = lane >> 2, tig = lane & 3;
    const int wm   = wid >> 2,  wn  = wid & 3;
    const int bm   = blockIdx.y * BM, bn = blockIdx.x * BN;
    const uint32_t sbase = smem_u32(dsm);

    const int lrow = lane & 15;
    const int lkof = (lane >> 4) * 16;

    float acc[MT][NT][4];
#pragma unroll
    for (int i = 0; i < MT; i++)
#pragma unroll
        for (int j = 0; j < NT; j++)
#pragma unroll
            for (int q = 0; q < 4; q++) acc[i][j][q] = 0.0f;

#define PREFETCH(c)                                                            \
    {                                                                          \
        const uint32_t _sb = sbase + ((c) % S) * STAGE;                        \
        const int _kk = (c) * 32;                                              \
        {                                                                      \
            const int _r = tid >> 2, _ch = tid & 3;                            \
            const uint32_t _d = _sb + _r * 80 + _ch * 16;                      \
            const size_t _o = (size_t)(bm + _r) * K + _kk + _ch * 8;           \
            asm volatile("cp.async.ca.shared.global [%0], [%1], 16;"           \
                         :: "r"(_d), "l"(Ahi + _o));                           \
            asm volatile("cp.async.ca.shared.global [%0], [%1], 16;"           \
                         :: "r"(_d + AT), "l"(Alo + _o));                      \
        }                                                                      \
        _Pragma("unroll")                                                      \
        for (int _i = 0; _i < BCH; _i++) {                                     \
            const int _u = tid + _i * 256;                                     \
            const int _r = _u >> 2, _ch = _u & 3;                              \
            const uint32_t _d = _sb + 2 * AT + _r * 80 + _ch * 16;             \
            const size_t _o = (size_t)(bn + _r) * K + _kk + _ch * 8;           \
            asm volatile("cp.async.ca.shared.global [%0], [%1], 16;"           \
                         :: "r"(_d), "l"(Bhi + _o));                           \
            asm volatile("cp.async.ca.shared.global [%0], [%1], 16;"           \
                         :: "r"(_d + BT), "l"(Blo + _o));                      \
        }                                                                      \
    }

#pragma unroll
    for (int i = 0; i < S - 1; i++) {
        PREFETCH(i);
        asm volatile("cp.async.commit_group;" ::: "memory");
    }

    for (int c = 0; c < NCH; c++) {
        asm volatile("cp.async.wait_group %0;" :: "n"(S - 2) : "memory");
        __syncthreads();

        if (c + S - 1 < NCH) PREFETCH(c + S - 1);
        asm volatile("cp.async.commit_group;" ::: "memory");

        const uint32_t sb  = sbase + (c % S) * STAGE;
        const uint32_t aBh = sb + (uint32_t)(wm * 32 + lrow) * 80 + lkof;
        const uint32_t bBh = sb + 2 * AT + (uint32_t)(wn * WN + lrow) * 80 + lkof;

#pragma unroll
        for (int ks = 0; ks < 2; ks++) {
            uint32_t ah[MT][4], al[MT][4], bh[NT][2], bl[NT][2];
#pragma unroll
            for (int mt = 0; mt < MT; mt++) {
                ldsm_x4(aBh + mt * 16 * 80 + ks * 32, ah[mt]);
                ldsm_x4(aBh + AT + mt * 16 * 80 + ks * 32, al[mt]);
            }
#pragma unroll
            for (int p = 0; p < NP; p++) {
                uint32_t r[4];
                ldsm_x4(bBh + p * 16 * 80 + ks * 32, r);
                bh[2 * p + 0][0] = r[0]; bh[2 * p + 1][0] = r[1];
                bh[2 * p + 0][1] = r[2]; bh[2 * p + 1][1] = r[3];
                ldsm_x4(bBh + BT + p * 16 * 80 + ks * 32, r);
                bl[2 * p + 0][0] = r[0]; bl[2 * p + 1][0] = r[1];
                bl[2 * p + 0][1] = r[2]; bl[2 * p + 1][1] = r[3];
            }
#pragma unroll
            for (int mt = 0; mt < MT; mt++)
#pragma unroll
                for (int nt = 0; nt < NT; nt++) {
                    mma_bf16(acc[mt][nt], ah[mt], bh[nt]);
                    mma_bf16(acc[mt][nt], al[mt], bh[nt]);
                    mma_bf16(acc[mt][nt], ah[mt], bl[nt]);
                }
        }
    }
#undef PREFETCH

#pragma unroll
    for (int mt = 0; mt < MT; mt++) {
#pragma unroll
        for (int nt = 0; nt < NT; nt++) {
            const int m = bm + wm * 32 + mt * 16 + gid;
            const int n = bn + wn * WN + nt * 8 + 2 * tig;
            float b0 = bias ? bias[n] : 0.0f;
            float b1 = bias ? bias[n + 1] : 0.0f;
            float2 v0 = make_float2(acc[mt][nt][0] + b0, acc[mt][nt][1] + b1);
            float2 v1 = make_float2(acc[mt][nt][2] + b0, acc[mt][nt][3] + b1);
            *reinterpret_cast<float2*>(&C[(size_t)m * N + n]) = v0;
            *reinterpret_cast<float2*>(&C[(size_t)(m + 8) * N + n]) = v1;
        }
    }
}

// ---------------------------------------------------------------------------
// Attention (unchanged): block per query, warp = head.
// ---------------------------------------------------------------------------
__device__ __forceinline__ float warpSum(float v) {
#pragma unroll
    for (int o = 16; o > 0; o >>= 1) v += __shfl_xor_sync(0xffffffffu, v, o);
    return v;
}
__device__ __forceinline__ float warpMax(float v) {
#pragma unroll
    for (int o = 16; o > 0; o >>= 1) v = fmaxf(v, __shfl_xor_sync(0xffffffffu, v, o));
    return v;
}

__device__ __forceinline__ void pack_hilo(float4 v, uint2& hi, uint2& lo) {
    unsigned short h[4], l[4];
    float vv[4] = {v.x, v.y, v.z, v.w};
#pragma unroll
    for (int j = 0; j < 4; j++) {
        __nv_bfloat16 hb = __float2bfloat16_rn(vv[j]);
        h[j] = __bfloat16_as_ushort(hb);
        l[j] = __bfloat16_as_ushort(__float2bfloat16_rn(vv[j] - __bfloat162float(hb)));
    }
    hi = make_uint2((uint32_t)h[0] | ((uint32_t)h[1] << 16),
                    (uint32_t)h[2] | ((uint32_t)h[3] << 16));
    lo = make_uint2((uint32_t)l[0] | ((uint32_t)l[1] << 16),
                    (uint32_t)l[2] | ((uint32_t)l[3] << 16));
}

__global__ void __launch_bounds__(256)
attn_kernel(const float* __restrict__ qkv,
            __nv_bfloat16* __restrict__ ahi, __nv_bfloat16* __restrict__ alo) {
    __shared__ float sims[HEADS][128];
    __shared__ int   rows[HEADS][128];

    const int bid = blockIdx.x;
    const int tid = threadIdx.x;

    if (bid == 2047) {
        for (int c = tid; c < INNER; c += 256) {
            float v = qkv[2 * INNER + c];
            __nv_bfloat16 hb = __float2bfloat16_rn(v);
            ahi[c] = hb;
            alo[c] = __float2bfloat16_rn(v - __bfloat162float(hb));
        }
        return;
    }

    const int qi   = bid;
    const int h    = tid >> 5;
    const int lane = tid & 31;
    const int g    = lane >> 3;
    const int li   = lane & 7;

    const float* qrow = qkv + (size_t)(qi + 1) * QKVW + h * DHEAD;
    float4 q4a = *reinterpret_cast<const float4*>(qrow + li * 4);
    float4 q4b = *reinterpret_cast<const float4*>(qrow + 32 + li * 4);
    const float sc = 0.125f;
    q4a.x *= sc; q4a.y *= sc; q4a.z *= sc; q4a.w *= sc;
    q4b.x *= sc; q4b.y *= sc; q4b.z *= sc; q4b.w *= sc;

    const int f  = qi >> 10;
    const int yy = (qi >> 5) & 31;
    const int xx = qi & 31;

    const float* kbase = qkv + INNER;
    const float* vbase = qkv + 2 * INNER;

#pragma unroll 4
    for (int it = 0; it < 32; it++) {
        const int s = it * 4 + g;
        int row = 0;
        bool valid;
        if (s == 0) {
            valid = true;
        } else {
            const int jj = s - 1;
            const int df = jj / 25;
            const int rem = jj - df * 25;
            const int dh = rem / 5;
            const int dw = rem - dh * 5;
            const int nf = f + df - 2, nh = yy + dh - 2, nw = xx + dw - 2;
            valid = (jj < 125) & ((unsigned)nf < 2u) & ((unsigned)nh < 32u) &
                    ((unsigned)nw < 32u);
            const int nidx = (nf << 10) + (nh << 5) + nw;
            valid = valid && (nidx <= qi);
            row = nidx + 1;
        }
        float part = 0.0f;
        if (valid) {
            const float* kr = kbase + (size_t)row * QKVW + h * DHEAD;
            float4 k4a = *reinterpret_cast<const float4*>(kr + li * 4);
            float4 k4b = *reinterpret_cast<const float4*>(kr + 32 + li * 4);
            part = q4a.x * k4a.x + q4a.y * k4a.y + q4a.z * k4a.z + q4a.w * k4a.w +
                   q4b.x * k4b.x + q4b.y * k4b.y + q4b.z * k4b.z + q4b.w * k4b.w;
        }
        part += __shfl_xor_sync(0xffffffffu, part, 1);
        part += __shfl_xor_sync(0xffffffffu, part, 2);
        part += __shfl_xor_sync(0xffffffffu, part, 4);
        if (li == 0) {
            sims[h][s] = valid ? part : -FLT_MAX;
            rows[h][s] = row;
        }
    }
    __syncwarp();

    float sv[4];
#pragma unroll
    for (int t = 0; t < 4; t++) {
        const int s = lane + 32 * t;
        sv[t] = (s < 126) ? sims[h][s] : -FLT_MAX;
    }
    float m = fmaxf(fmaxf(sv[0], sv[1]), fmaxf(sv[2], sv[3]));
    m = warpMax(m);
    float z = 0.0f;
#pragma unroll
    for (int t = 0; t < 4; t++) {
        sv[t] = __expf(sv[t] - m);
        z += sv[t];
    }
    z = warpSum(z);
    const float invz = 1.0f / z;
#pragma unroll
    for (int t = 0; t < 4; t++) {
        const int s = lane + 32 * t;
        if (s < 126) sims[h][s] = sv[t] * invz;
    }
    __syncwarp();

    float4 aa = make_float4(0.f, 0.f, 0.f, 0.f);
    float4 ab = make_float4(0.f, 0.f, 0.f, 0.f);
#pragma unroll 4
    for (int it = 0; it < 32; it++) {
        const int s = it * 4 + g;
        if (s < 126) {
            const float p = sims[h][s];
            if (p != 0.0f) {
                const int row = rows[h][s];
                const float* vr = vbase + (size_t)row * QKVW + h * DHEAD;
                float4 v4a = *reinterpret_cast<const float4*>(vr + li * 4);
                float4 v4b = *reinterpret_cast<const float4*>(vr + 32 + li * 4);
                aa.x = fmaf(p, v4a.x, aa.x); aa.y = fmaf(p, v4a.y, aa.y);
                aa.z = fmaf(p, v4a.z, aa.z); aa.w = fmaf(p, v4a.w, aa.w);
                ab.x = fmaf(p, v4b.x, ab.x); ab.y = fmaf(p, v4b.y, ab.y);
                ab.z = fmaf(p, v4b.z, ab.z); ab.w = fmaf(p, v4b.w, ab.w);
            }
        }
    }

#pragma unroll
    for (int off = 8; off <= 16; off <<= 1) {
        aa.x += __shfl_xor_sync(0xffffffffu, aa.x, off);
        aa.y += __shfl_xor_sync(0xffffffffu, aa.y, off);
        aa.z += __shfl_xor_sync(0xffffffffu, aa.z, off);
        aa.w += __shfl_xor_sync(0xffffffffu, aa.w, off);
        ab.x += __shfl_xor_sync(0xffffffffu, ab.x, off);
        ab.y += __shfl_xor_sync(0xffffffffu, ab.y, off);
        ab.z += __shfl_xor_sync(0xffffffffu, ab.z, off);
        ab.w += __shfl_xor_sync(0xffffffffu, ab.w, off);
    }

    if (g == 0) {
        const size_t obase = (size_t)(qi + 1) * INNER + h * DHEAD;
        uint2 hi, lo;
        pack_hilo(aa, hi, lo);
        *reinterpret_cast<uint2*>(ahi + obase + li * 4) = hi;
        *reinterpret_cast<uint2*>(alo + obase + li * 4) = lo;
        pack_hilo(ab, hi, lo);
        *reinterpret_cast<uint2*>(ahi + obase + 32 + li * 4) = hi;
        *reinterpret_cast<uint2*>(alo + obase + 32 + li * 4) = lo;
    }
}

// ---------------------------------------------------------------------------
extern "C" void kernel_launch(void* const* d_in, const int* in_sizes, int n_in,
                              void* d_out, int out_size) {
    const float* x     = (const float*)d_in[0];  // (1, 2048, 512)
    const float* w_qkv = (const float*)d_in[1];  // (512, 1536)
    const float* w_out = (const float*)d_in[2];  // (512, 512)
    const float* b_out = (const float*)d_in[3];  // (512,)
    float* out = (float*)d_out;

    float* qkv;
    __nv_bfloat16 *xhi, *xlo, *w1hiT, *w1loT, *ahi, *alo, *w2hiT, *w2loT;
    cudaGetSymbolAddress((void**)&qkv,   g_qkv);
    cudaGetSymbolAddress((void**)&xhi,   g_xhi);
    cudaGetSymbolAddress((void**)&xlo,   g_xlo);
    cudaGetSymbolAddress((void**)&w1hiT, g_w1hiT);
    cudaGetSymbolAddress((void**)&w1loT, g_w1loT);
    cudaGetSymbolAddress((void**)&ahi,   g_ahi);
    cudaGetSymbolAddress((void**)&alo,   g_alo);
    cudaGetSymbolAddress((void**)&w2hiT, g_w2hiT);
    cudaGetSymbolAddress((void**)&w2loT, g_w2loT);

    // stage bytes: 2*A(5120) + 2*B(BN*80)
    const int smem1 = 3 * (2 * 5120 + 2 * 128 * 80);   // 92160, BN=128, S=3
    const int smem2 = 4 * (2 * 5120 + 2 * 64 * 80);    // 81920, BN=64,  S=4
    cudaFuncSetAttribute((const void*)gemm_so_kernel<128, 3>,
                         cudaFuncAttributeMaxDynamicSharedMemorySize, smem1);
    cudaFuncSetAttribute((const void*)gemm_so_kernel<64, 4>,
                         cudaFuncAttributeMaxDynamicSharedMemorySize, smem2);

    // split x (layout preserved); transpose-split weights to [N, K]
    split_bf16_kernel<<<(NTOK * INNER / 4 + 255) / 256, 256>>>(x, xhi, xlo,
                                                               NTOK * INNER);
    tsplit_kernel<<<dim3(QKVW / 32, KDIM / 32), 256>>>(w_qkv, w1hiT, w1loT,
                                                       KDIM, QKVW);
    tsplit_kernel<<<dim3(INNER / 32, KDIM / 32), 256>>>(w_out, w2hiT, w2loT,
                                                        KDIM, INNER);

    // 1) qkv = x @ w_qkv   (bf16x3 shared-operand pipeline)
    gemm_so_kernel<128, 3><<<dim3(QKVW / 128, NTOK / 64), 256, smem1>>>(
        xhi, xlo, w1hiT, w1loT, qkv, nullptr, QKVW);

    // 2) windowed causal attention (writes bf16 hi/lo directly)
    attn_kernel<<<2048, 256>>>(qkv, ahi, alo);

    // 3) out = attn @ w_out + b_out
    gemm_so_kernel<64, 4><<<dim3(INNER / 64, NTOK / 64), 256, smem2>>>(
        ahi, alo, w2hiT, w2loT, out, b_out, INNER);
}

// round 9
// speedup vs baseline: 2.3026x; 1.0253x over previous
#include <cuda_runtime.h>
#include <cuda_bf16.h>
#include <cstdint>
#include <float.h>
#include <math.h>

// Problem constants
#define NTOK   2048          // N = F*H*W = 2*32*32
#define INNER  512
#define QKVW   1536          // 3*INNER
#define HEADS  8
#define DHEAD  64
#define KDIM   512           // GEMM K for both GEMMs

// Scratch (device globals; no allocation allowed)
__device__ float g_qkv[NTOK * QKVW];
__device__ __nv_bfloat16 g_xhi[NTOK * INNER],    g_xlo[NTOK * INNER];
__device__ __nv_bfloat16 g_w1hiT[QKVW * INNER],  g_w1loT[QKVW * INNER];   // [N,K]
__device__ __nv_bfloat16 g_ahi[NTOK * INNER],    g_alo[NTOK * INNER];
__device__ __nv_bfloat16 g_w2hiT[INNER * INNER], g_w2loT[INNER * INNER];  // [N,K]

// ---------------------------------------------------------------------------
// Split fp32 -> (hi, lo) bf16, same layout
// ---------------------------------------------------------------------------
__global__ void __launch_bounds__(256)
split_bf16_kernel(const float* __restrict__ in,
                  __nv_bfloat16* __restrict__ hi,
                  __nv_bfloat16* __restrict__ lo, int n) {
    int base = (blockIdx.x * 256 + threadIdx.x) * 4;
    if (base < n) {
        float4 v = *reinterpret_cast<const float4*>(in + base);
        float vv[4] = {v.x, v.y, v.z, v.w};
        unsigned short h[4], l[4];
#pragma unroll
        for (int j = 0; j < 4; j++) {
            __nv_bfloat16 hb = __float2bfloat16_rn(vv[j]);
            h[j] = __bfloat16_as_ushort(hb);
            l[j] = __bfloat16_as_ushort(__float2bfloat16_rn(vv[j] - __bfloat162float(hb)));
        }
        uint2 ho = make_uint2((uint32_t)h[0] | ((uint32_t)h[1] << 16),
                              (uint32_t)h[2] | ((uint32_t)h[3] << 16));
        uint2 lz = make_uint2((uint32_t)l[0] | ((uint32_t)l[1] << 16),
                              (uint32_t)l[2] | ((uint32_t)l[3] << 16));
        *reinterpret_cast<uint2*>(hi + base) = ho;
        *reinterpret_cast<uint2*>(lo + base) = lz;
    }
}

// ---------------------------------------------------------------------------
// Transpose + split: in [K, N] fp32 -> hiT/loT [N, K] bf16
// ---------------------------------------------------------------------------
__global__ void __launch_bounds__(256)
tsplit_kernel(const float* __restrict__ in, __nv_bfloat16* __restrict__ hiT,
              __nv_bfloat16* __restrict__ loT, int K, int N) {
    __shared__ float sm[32][33];
    const int n0 = blockIdx.x * 32, k0 = blockIdx.y * 32;
    const int tx = threadIdx.x & 31, ty = threadIdx.x >> 5;
#pragma unroll
    for (int i = 0; i < 4; i++)
        sm[ty + i * 8][tx] = in[(size_t)(k0 + ty + i * 8) * N + n0 + tx];
    __syncthreads();
#pragma unroll
    for (int i = 0; i < 4; i++) {
        int nr = ty + i * 8;
        float v = sm[tx][nr];
        __nv_bfloat16 hb = __float2bfloat16_rn(v);
        hiT[(size_t)(n0 + nr) * K + k0 + tx] = hb;
        loT[(size_t)(n0 + nr) * K + k0 + tx] =
            __float2bfloat16_rn(v - __bfloat162float(hb));
    }
}

// ---------------------------------------------------------------------------
// bf16x3 shared-operand GEMM:
//   per k-chunk load Ahi/Alo/Bhi/Blo ONCE, run 3 MMA combos into one acc:
//   C = Ahi*Bhi + Alo*Bhi + Ahi*Blo (+bias)
// MMAs issued combo-major so same-accumulator reuse distance is 8 MMAs.
// CTA tile 64 x BN, BK=32, 8 warps (2x4), warp tile 32 x (BN/4).
// smem rows padded to 80B: conflict-free for cp.async and ldmatrix.
// ---------------------------------------------------------------------------
__device__ __forceinline__ void mma_bf16(float* c, const uint32_t* a, const uint32_t* b) {
    asm volatile(
        "mma.sync.aligned.m16n8k16.row.col.f32.bf16.bf16.f32 "
        "{%0,%1,%2,%3}, {%4,%5,%6,%7}, {%8,%9}, {%0,%1,%2,%3};\n"
        : "+f"(c[0]), "+f"(c[1]), "+f"(c[2]), "+f"(c[3])
        : "r"(a[0]), "r"(a[1]), "r"(a[2]), "r"(a[3]), "r"(b[0]), "r"(b[1]));
}

__device__ __forceinline__ void ldsm_x4(uint32_t addr, uint32_t* r) {
    asm volatile("ldmatrix.sync.aligned.m8n8.x4.shared.b16 {%0,%1,%2,%3}, [%4];"
                 : "=r"(r[0]), "=r"(r[1]), "=r"(r[2]), "=r"(r[3]) : "r"(addr));
}

__device__ __forceinline__ uint32_t smem_u32(const void* p) {
    uint32_t a;
    asm("{ .reg .u64 t; cvta.to.shared.u64 t, %1; cvt.u32.u64 %0, t; }"
        : "=r"(a) : "l"(p));
    return a;
}

template <int BN, int S, int MB>
__global__ void __launch_bounds__(256, MB)
gemm_so_kernel(const __nv_bfloat16* __restrict__ Ahi,
               const __nv_bfloat16* __restrict__ Alo,
               const __nv_bfloat16* __restrict__ Bhi,
               const __nv_bfloat16* __restrict__ Blo,
               float* __restrict__ C, const float* __restrict__ bias, int N) {
    constexpr int BM = 64, K = KDIM;
    constexpr int AT = BM * 80;                  // one A tile bytes (5120)
    constexpr int BT = BN * 80;                  // one B tile bytes
    constexpr int STAGE = 2 * AT + 2 * BT;       // Ahi|Alo|Bhi|Blo
    constexpr int NCH = K / 32;                  // 16
    constexpr int WN = BN / 4;
    constexpr int MT = 2, NT = WN / 8, NP = NT / 2;
    constexpr int BCH = BN * 4 / 256;            // B 16B-chunks per thread

    extern __shared__ char dsm[];

    const int tid  = threadIdx.x;
    const int lane = tid & 31, wid = tid >> 5;
    const int gid  = lane >> 2, tig = lane & 3;
    const int wm   = wid >> 2,  wn  = wid & 3;
    const int bm   = blockIdx.y * BM, bn = blockIdx.x * BN;
    const uint32_t sbase = smem_u32(dsm);

    const int lrow = lane & 15;
    const int lkof = (lane >> 4) * 16;

    float acc[MT][NT][4];
#pragma unroll
    for (int i = 0; i < MT; i++)
#pragma unroll
        for (int j = 0; j < NT; j++)
#pragma unroll
            for (int q = 0; q < 4; q++) acc[i][j][q] = 0.0f;

#define PREFETCH(c)                                                            \
    {                                                                          \
        const uint32_t _sb = sbase + ((c) % S) * STAGE;                        \
        const int _kk = (c) * 32;                                              \
        {                                                                      \
            const int _r = tid >> 2, _ch = tid & 3;                            \
            const uint32_t _d = _sb + _r * 80 + _ch * 16;                      \
            const size_t _o = (size_t)(bm + _r) * K + _kk + _ch * 8;           \
            asm volatile("cp.async.ca.shared.global [%0], [%1], 16;"           \
                         :: "r"(_d), "l"(Ahi + _o));                           \
            asm volatile("cp.async.ca.shared.global [%0], [%1], 16;"           \
                         :: "r"(_d + AT), "l"(Alo + _o));                      \
        }                                                                      \
        _Pragma("unroll")                                                      \
        for (int _i = 0; _i < BCH; _i++) {                                     \
            const int _u = tid + _i * 256;                                     \
            const int _r = _u >> 2, _ch = _u & 3;                              \
            const uint32_t _d = _sb + 2 * AT + _r * 80 + _ch * 16;             \
            const size_t _o = (size_t)(bn + _r) * K + _kk + _ch * 8;           \
            asm volatile("cp.async.ca.shared.global [%0], [%1], 16;"           \
                         :: "r"(_d), "l"(Bhi + _o));                           \
            asm volatile("cp.async.ca.shared.global [%0], [%1], 16;"           \
                         :: "r"(_d + BT), "l"(Blo + _o));                      \
        }                                                                      \
    }

#pragma unroll
    for (int i = 0; i < S - 1; i++) {
        PREFETCH(i);
        asm volatile("cp.async.commit_group;" ::: "memory");
    }

    for (int c = 0; c < NCH; c++) {
        asm volatile("cp.async.wait_group %0;" :: "n"(S - 2) : "memory");
        __syncthreads();

        if (c + S - 1 < NCH) PREFETCH(c + S - 1);
        asm volatile("cp.async.commit_group;" ::: "memory");

        const uint32_t sb  = sbase + (c % S) * STAGE;
        const uint32_t aBh = sb + (uint32_t)(wm * 32 + lrow) * 80 + lkof;
        const uint32_t bBh = sb + 2 * AT + (uint32_t)(wn * WN + lrow) * 80 + lkof;

#pragma unroll
        for (int ks = 0; ks < 2; ks++) {
            uint32_t ah[MT][4], al[MT][4], bh[NT][2], bl[NT][2];
#pragma unroll
            for (int mt = 0; mt < MT; mt++) {
                ldsm_x4(aBh + mt * 16 * 80 + ks * 32, ah[mt]);
                ldsm_x4(aBh + AT + mt * 16 * 80 + ks * 32, al[mt]);
            }
#pragma unroll
            for (int p = 0; p < NP; p++) {
                uint32_t r[4];
                ldsm_x4(bBh + p * 16 * 80 + ks * 32, r);
                bh[2 * p + 0][0] = r[0]; bh[2 * p + 1][0] = r[1];
                bh[2 * p + 0][1] = r[2]; bh[2 * p + 1][1] = r[3];
                ldsm_x4(bBh + BT + p * 16 * 80 + ks * 32, r);
                bl[2 * p + 0][0] = r[0]; bl[2 * p + 1][0] = r[1];
                bl[2 * p + 0][1] = r[2]; bl[2 * p + 1][1] = r[3];
            }
            // combo-major: same-acc reuse distance = MT*NT MMAs
#pragma unroll
            for (int mt = 0; mt < MT; mt++)
#pragma unroll
                for (int nt = 0; nt < NT; nt++)
                    mma_bf16(acc[mt][nt], ah[mt], bh[nt]);
#pragma unroll
            for (int mt = 0; mt < MT; mt++)
#pragma unroll
                for (int nt = 0; nt < NT; nt++)
                    mma_bf16(acc[mt][nt], al[mt], bh[nt]);
#pragma unroll
            for (int mt = 0; mt < MT; mt++)
#pragma unroll
                for (int nt = 0; nt < NT; nt++)
                    mma_bf16(acc[mt][nt], ah[mt], bl[nt]);
        }
    }
#undef PREFETCH

#pragma unroll
    for (int mt = 0; mt < MT; mt++) {
#pragma unroll
        for (int nt = 0; nt < NT; nt++) {
            const int m = bm + wm * 32 + mt * 16 + gid;
            const int n = bn + wn * WN + nt * 8 + 2 * tig;
            float b0 = bias ? bias[n] : 0.0f;
            float b1 = bias ? bias[n + 1] : 0.0f;
            float2 v0 = make_float2(acc[mt][nt][0] + b0, acc[mt][nt][1] + b1);
            float2 v1 = make_float2(acc[mt][nt][2] + b0, acc[mt][nt][3] + b1);
            *reinterpret_cast<float2*>(&C[(size_t)m * N + n]) = v0;
            *reinterpret_cast<float2*>(&C[(size_t)(m + 8) * N + n]) = v1;
        }
    }
}

// ---------------------------------------------------------------------------
// Attention (unchanged): block per query, warp = head.
// ---------------------------------------------------------------------------
__device__ __forceinline__ float warpSum(float v) {
#pragma unroll
    for (int o = 16; o > 0; o >>= 1) v += __shfl_xor_sync(0xffffffffu, v, o);
    return v;
}
__device__ __forceinline__ float warpMax(float v) {
#pragma unroll
    for (int o = 16; o > 0; o >>= 1) v = fmaxf(v, __shfl_xor_sync(0xffffffffu, v, o));
    return v;
}

__device__ __forceinline__ void pack_hilo(float4 v, uint2& hi, uint2& lo) {
    unsigned short h[4], l[4];
    float vv[4] = {v.x, v.y, v.z, v.w};
#pragma unroll
    for (int j = 0; j < 4; j++) {
        __nv_bfloat16 hb = __float2bfloat16_rn(vv[j]);
        h[j] = __bfloat16_as_ushort(hb);
        l[j] = __bfloat16_as_ushort(__float2bfloat16_rn(vv[j] - __bfloat162float(hb)));
    }
    hi = make_uint2((uint32_t)h[0] | ((uint32_t)h[1] << 16),
                    (uint32_t)h[2] | ((uint32_t)h[3] << 16));
    lo = make_uint2((uint32_t)l[0] | ((uint32_t)l[1] << 16),
                    (uint32_t)l[2] | ((uint32_t)l[3] << 16));
}

__global__ void __launch_bounds__(256)
attn_kernel(const float* __restrict__ qkv,
            __nv_bfloat16* __restrict__ ahi, __nv_bfloat16* __restrict__ alo) {
    __shared__ float sims[HEADS][128];
    __shared__ int   rows[HEADS][128];

    const int bid = blockIdx.x;
    const int tid = threadIdx.x;

    if (bid == 2047) {
        for (int c = tid; c < INNER; c += 256) {
            float v = qkv[2 * INNER + c];
            __nv_bfloat16 hb = __float2bfloat16_rn(v);
            ahi[c] = hb;
            alo[c] = __float2bfloat16_rn(v - __bfloat162float(hb));
        }
        return;
    }

    const int qi   = bid;
    const int h    = tid >> 5;
    const int lane = tid & 31;
    const int g    = lane >> 3;
    const int li   = lane & 7;

    const float* qrow = qkv + (size_t)(qi + 1) * QKVW + h * DHEAD;
    float4 q4a = *reinterpret_cast<const float4*>(qrow + li * 4);
    float4 q4b = *reinterpret_cast<const float4*>(qrow + 32 + li * 4);
    const float sc = 0.125f;
    q4a.x *= sc; q4a.y *= sc; q4a.z *= sc; q4a.w *= sc;
    q4b.x *= sc; q4b.y *= sc; q4b.z *= sc; q4b.w *= sc;

    const int f  = qi >> 10;
    const int yy = (qi >> 5) & 31;
    const int xx = qi & 31;

    const float* kbase = qkv + INNER;
    const float* vbase = qkv + 2 * INNER;

#pragma unroll 4
    for (int it = 0; it < 32; it++) {
        const int s = it * 4 + g;
        int row = 0;
        bool valid;
        if (s == 0) {
            valid = true;
        } else {
            const int jj = s - 1;
            const int df = jj / 25;
            const int rem = jj - df * 25;
            const int dh = rem / 5;
            const int dw = rem - dh * 5;
            const int nf = f + df - 2, nh = yy + dh - 2, nw = xx + dw - 2;
            valid = (jj < 125) & ((unsigned)nf < 2u) & ((unsigned)nh < 32u) &
                    ((unsigned)nw < 32u);
            const int nidx = (nf << 10) + (nh << 5) + nw;
            valid = valid && (nidx <= qi);
            row = nidx + 1;
        }
        float part = 0.0f;
        if (valid) {
            const float* kr = kbase + (size_t)row * QKVW + h * DHEAD;
            float4 k4a = *reinterpret_cast<const float4*>(kr + li * 4);
            float4 k4b = *reinterpret_cast<const float4*>(kr + 32 + li * 4);
            part = q4a.x * k4a.x + q4a.y * k4a.y + q4a.z * k4a.z + q4a.w * k4a.w +
                   q4b.x * k4b.x + q4b.y * k4b.y + q4b.z * k4b.z + q4b.w * k4b.w;
        }
        part += __shfl_xor_sync(0xffffffffu, part, 1);
        part += __shfl_xor_sync(0xffffffffu, part, 2);
        part += __shfl_xor_sync(0xffffffffu, part, 4);
        if (li == 0) {
            sims[h][s] = valid ? part : -FLT_MAX;
            rows[h][s] = row;
        }
    }
    __syncwarp();

    float sv[4];
#pragma unroll
    for (int t = 0; t < 4; t++) {
        const int s = lane + 32 * t;
        sv[t] = (s < 126) ? sims[h][s] : -FLT_MAX;
    }
    float m = fmaxf(fmaxf(sv[0], sv[1]), fmaxf(sv[2], sv[3]));
    m = warpMax(m);
    float z = 0.0f;
#pragma unroll
    for (int t = 0; t < 4; t++) {
        sv[t] = __expf(sv[t] - m);
        z += sv[t];
    }
    z = warpSum(z);
    const float invz = 1.0f / z;
#pragma unroll
    for (int t = 0; t < 4; t++) {
        const int s = lane + 32 * t;
        if (s < 126) sims[h][s] = sv[t] * invz;
    }
    __syncwarp();

    float4 aa = make_float4(0.f, 0.f, 0.f, 0.f);
    float4 ab = make_float4(0.f, 0.f, 0.f, 0.f);
#pragma unroll 4
    for (int it = 0; it < 32; it++) {
        const int s = it * 4 + g;
        if (s < 126) {
            const float p = sims[h][s];
            if (p != 0.0f) {
                const int row = rows[h][s];
                const float* vr = vbase + (size_t)row * QKVW + h * DHEAD;
                float4 v4a = *reinterpret_cast<const float4*>(vr + li * 4);
                float4 v4b = *reinterpret_cast<const float4*>(vr + 32 + li * 4);
                aa.x = fmaf(p, v4a.x, aa.x); aa.y = fmaf(p, v4a.y, aa.y);
                aa.z = fmaf(p, v4a.z, aa.z); aa.w = fmaf(p, v4a.w, aa.w);
                ab.x = fmaf(p, v4b.x, ab.x); ab.y = fmaf(p, v4b.y, ab.y);
                ab.z = fmaf(p, v4b.z, ab.z); ab.w = fmaf(p, v4b.w, ab.w);
            }
        }
    }

#pragma unroll
    for (int off = 8; off <= 16; off <<= 1) {
        aa.x += __shfl_xor_sync(0xffffffffu, aa.x, off);
        aa.y += __shfl_xor_sync(0xffffffffu, aa.y, off);
        aa.z += __shfl_xor_sync(0xffffffffu, aa.z, off);
        aa.w += __shfl_xor_sync(0xffffffffu, aa.w, off);
        ab.x += __shfl_xor_sync(0xffffffffu, ab.x, off);
        ab.y += __shfl_xor_sync(0xffffffffu, ab.y, off);
        ab.z += __shfl_xor_sync(0xffffffffu, ab.z, off);
        ab.w += __shfl_xor_sync(0xffffffffu, ab.w, off);
    }

    if (g == 0) {
        const size_t obase = (size_t)(qi + 1) * INNER + h * DHEAD;
        uint2 hi, lo;
        pack_hilo(aa, hi, lo);
        *reinterpret_cast<uint2*>(ahi + obase + li * 4) = hi;
        *reinterpret_cast<uint2*>(alo + obase + li * 4) = lo;
        pack_hilo(ab, hi, lo);
        *reinterpret_cast<uint2*>(ahi + obase + 32 + li * 4) = hi;
        *reinterpret_cast<uint2*>(alo + obase + 32 + li * 4) = lo;
    }
}

// ---------------------------------------------------------------------------
extern "C" void kernel_launch(void* const* d_in, const int* in_sizes, int n_in,
                              void* d_out, int out_size) {
    const float* x     = (const float*)d_in[0];  // (1, 2048, 512)
    const float* w_qkv = (const float*)d_in[1];  // (512, 1536)
    const float* w_out = (const float*)d_in[2];  // (512, 512)
    const float* b_out = (const float*)d_in[3];  // (512,)
    float* out = (float*)d_out;

    float* qkv;
    __nv_bfloat16 *xhi, *xlo, *w1hiT, *w1loT, *ahi, *alo, *w2hiT, *w2loT;
    cudaGetSymbolAddress((void**)&qkv,   g_qkv);
    cudaGetSymbolAddress((void**)&xhi,   g_xhi);
    cudaGetSymbolAddress((void**)&xlo,   g_xlo);
    cudaGetSymbolAddress((void**)&w1hiT, g_w1hiT);
    cudaGetSymbolAddress((void**)&w1loT, g_w1loT);
    cudaGetSymbolAddress((void**)&ahi,   g_ahi);
    cudaGetSymbolAddress((void**)&alo,   g_alo);
    cudaGetSymbolAddress((void**)&w2hiT, g_w2hiT);
    cudaGetSymbolAddress((void**)&w2loT, g_w2loT);

    // stage bytes: 2*A(5120) + 2*B(BN*80)
    const int smem1 = 2 * (2 * 5120 + 2 * 128 * 80);   // 61440, BN=128, S=2 -> 3 CTAs/SM
    const int smem2 = 4 * (2 * 5120 + 2 * 64 * 80);    // 81920, BN=64,  S=4 -> 2 CTAs/SM
    cudaFuncSetAttribute((const void*)gemm_so_kernel<128, 2, 3>,
                         cudaFuncAttributeMaxDynamicSharedMemorySize, smem1);
    cudaFuncSetAttribute((const void*)gemm_so_kernel<64, 4, 2>,
                         cudaFuncAttributeMaxDynamicSharedMemorySize, smem2);

    // split x (layout preserved); transpose-split weights to [N, K]
    split_bf16_kernel<<<(NTOK * INNER / 4 + 255) / 256, 256>>>(x, xhi, xlo,
                                                               NTOK * INNER);
    tsplit_kernel<<<dim3(QKVW / 32, KDIM / 32), 256>>>(w_qkv, w1hiT, w1loT,
                                                       KDIM, QKVW);
    tsplit_kernel<<<dim3(INNER / 32, KDIM / 32), 256>>>(w_out, w2hiT, w2loT,
                                                        KDIM, INNER);

    // 1) qkv = x @ w_qkv   (bf16x3 shared-operand pipeline, 3 CTAs/SM)
    gemm_so_kernel<128, 2, 3><<<dim3(QKVW / 128, NTOK / 64), 256, smem1>>>(
        xhi, xlo, w1hiT, w1loT, qkv, nullptr, QKVW);

    // 2) windowed causal attention (writes bf16 hi/lo directly)
    attn_kernel<<<2048, 256>>>(qkv, ahi, alo);

    // 3) out = attn @ w_out + b_out
    gemm_so_kernel<64, 4, 2><<<dim3(INNER / 64, NTOK / 64), 256, smem2>>>(
        ahi, alo, w2hiT, w2loT, out, b_out, INNER);
}